// round 9
// baseline (speedup 1.0000x reference)
#include <cuda_runtime.h>
#include <cuda_bf16.h>
#include <float.h>
#include <stdint.h>

// Problem dims (fixed by setup_inputs)
#define NN   4096
#define FF   512
#define WRDS (NN / 32)
#define K3S  (3 * FF)      // 1536  packed K for feature-dim GEMMs
#define K3N  (3 * NN)      // 12288 logical K for the att@hk GEMM
#define KATT 8192          // physical att row stride: [hi(4096) | lo(4096)]
#define NSPLIT 4

// ---------------- device scratch (no allocations allowed) ----------------
__device__ float         g_Wh[NN * FF];
__device__ float         g_Wa[NN * FF];
__device__ float         g_hk[NN * FF];
__device__ float         g_src[NN];
__device__ float         g_dst[NN];
__device__ unsigned      g_Abits[NN * WRDS];
__device__ unsigned      g_P[NN * WRDS];
__device__ unsigned      g_Q[NN * WRDS];
__device__ float         g_S[(size_t)NN * NN];          // 64 MB scores
__device__ __nv_bfloat16 g_Xp [(size_t)NN * K3S];
__device__ __nv_bfloat16 g_WsP[(size_t)FF * K3S];
__device__ __nv_bfloat16 g_WlP[(size_t)FF * K3S];
__device__ __nv_bfloat16 g_hkP[(size_t)NN * K3S];
__device__ __nv_bfloat16 g_WaP[(size_t)NN * K3S];
__device__ __nv_bfloat16 g_hkTP[(size_t)FF * K3N];
__device__ __nv_bfloat16 g_attP[(size_t)NN * KATT];     // 64 MB [hi|lo]
__device__ float         g_part[NSPLIT][(size_t)NN * FF]; // 32 MB split-K partials

// ---------------- helpers ----------------
__device__ __forceinline__ float gelu_tanh(float x) {
    float x3 = x * x * x;
    return 0.5f * x * (1.0f + tanhf(0.7978845608028654f * (x + 0.044715f * x3)));
}
__device__ __forceinline__ uint32_t smem_u32(const void* p) {
    return (uint32_t)__cvta_generic_to_shared(p);
}

// ============================================================
// Tensor-core bf16 NT GEMM: C[M,N] = A[M,Kslice] * B[N,Kslice]^T
// CTA 128x128, 4 warps (2x2), warp tile 64x64, BK=64, 3-stage cp.async.
// DUAL:   blockIdx.z selects (B,C) vs (B2,C2)
// SPLITK: blockIdx.z selects K slice; C += z*M*N
// MASKED: reach-mask epilogue (masked -> -FLT_MAX)
// REMAP:  A-side logical k>=4096 reads physical k-4096 (hi-plane reuse)
// strideA: physical A row stride (== K unless REMAP)
// ============================================================
#define BK     64
#define SSTR   72            // padded halfs per row (144B, 16B multiple)
#define NSTG   3

template <bool MASKED, bool SPLITK, bool DUAL, bool REMAP>
__global__ void __launch_bounds__(128, 2) mma_gemm_nt(
    const __nv_bfloat16* __restrict__ A,
    const __nv_bfloat16* __restrict__ B,
    const __nv_bfloat16* __restrict__ B2,
    float* __restrict__ C,
    float* __restrict__ C2,
    int M, int N, int K, int kSlice, int strideA,
    const unsigned* __restrict__ maskbits)
{
    extern __shared__ __align__(16) unsigned char smem_raw[];
    __nv_bfloat16* AsBase = (__nv_bfloat16*)smem_raw;                 // [NSTG][128][SSTR]
    __nv_bfloat16* BsBase = AsBase + NSTG * 128 * SSTR;

    const int tid  = threadIdx.x;
    const int bx   = blockIdx.x;    // N tile
    const int by   = blockIdx.y;    // M tile
    const int bz   = blockIdx.z;
    const int warp = tid >> 5;
    const int lane = tid & 31;
    const int wm   = (warp >> 1) * 64;
    const int wn   = (warp & 1) * 64;

    const __nv_bfloat16* Bsel = (DUAL && bz) ? B2 : B;
    float* Csel = (DUAL && bz) ? C2 : C;
    int kBegin = 0, kLen = K;
    if (SPLITK) { kBegin = bz * kSlice; kLen = kSlice; Csel = C + (size_t)bz * M * N; }

    const __nv_bfloat16* Arow = A    + (size_t)(by * 128) * strideA;
    const __nv_bfloat16* Bg   = Bsel + (size_t)(bx * 128) * K + kBegin;

    float acc[4][8][4];
#pragma unroll
    for (int mi = 0; mi < 4; mi++)
#pragma unroll
        for (int nj = 0; nj < 8; nj++)
#pragma unroll
            for (int q = 0; q < 4; q++) acc[mi][nj][q] = 0.0f;

    const int nK = kLen / BK;   // BK=64 chunks

    auto load_stage = [&](int s, int kc) {
        __nv_bfloat16* As = AsBase + s * 128 * SSTR;
        __nv_bfloat16* Bs = BsBase + s * 128 * SSTR;
        int colL = kBegin + kc * BK;                    // logical A column
        int colP = REMAP ? (colL < NN ? colL : colL - NN) : colL;
#pragma unroll
        for (int j = 0; j < 8; j++) {
            int idx = tid + j * 128;        // 1024 chunks of 16B per matrix
            int row = idx >> 3;             // 0..127
            int c   = idx & 7;              // 16B chunk within 128B row
            uint32_t sa = smem_u32(&As[row * SSTR + c * 8]);
            const void* ga = Arow + (size_t)row * strideA + colP + c * 8;
            asm volatile("cp.async.cg.shared.global [%0], [%1], 16;" :: "r"(sa), "l"(ga));
            uint32_t sb = smem_u32(&Bs[row * SSTR + c * 8]);
            const void* gb = Bg + (size_t)row * K + kc * BK + c * 8;
            asm volatile("cp.async.cg.shared.global [%0], [%1], 16;" :: "r"(sb), "l"(gb));
        }
    };

    load_stage(0, 0);
    asm volatile("cp.async.commit_group;");
    if (nK > 1) {
        load_stage(1, 1);
        asm volatile("cp.async.commit_group;");
    }

    for (int kc = 0; kc < nK; kc++) {
        const int s = kc % NSTG;
        if (kc < nK - 1) {
            asm volatile("cp.async.wait_group 1;");
        } else {
            asm volatile("cp.async.wait_group 0;");
        }
        __syncthreads();
        // stage (kc+2)%NSTG is free: all warps finished compute kc-1 at this barrier
        if (kc + 2 < nK) {
            load_stage((kc + 2) % NSTG, kc + 2);
            asm volatile("cp.async.commit_group;");
        }

        const __nv_bfloat16* As = AsBase + s * 128 * SSTR;
        const __nv_bfloat16* Bs = BsBase + s * 128 * SSTR;

#pragma unroll
        for (int kk = 0; kk < BK; kk += 16) {
            uint32_t a[4][4];
#pragma unroll
            for (int mi = 0; mi < 4; mi++) {
                int row = wm + mi * 16 + (lane & 7) + ((lane >> 3) & 1) * 8;
                int col = kk + (lane >> 4) * 8;
                uint32_t addr = smem_u32(&As[row * SSTR + col]);
                asm volatile("ldmatrix.sync.aligned.m8n8.x4.shared.b16 {%0,%1,%2,%3},[%4];"
                    : "=r"(a[mi][0]), "=r"(a[mi][1]), "=r"(a[mi][2]), "=r"(a[mi][3])
                    : "r"(addr));
            }
            uint32_t b[8][2];
#pragma unroll
            for (int nj4 = 0; nj4 < 4; nj4++) {
                int row = wn + nj4 * 16 + (lane & 7) + (lane >> 4) * 8;
                int col = kk + ((lane >> 3) & 1) * 8;
                uint32_t addr = smem_u32(&Bs[row * SSTR + col]);
                asm volatile("ldmatrix.sync.aligned.m8n8.x4.shared.b16 {%0,%1,%2,%3},[%4];"
                    : "=r"(b[nj4 * 2][0]), "=r"(b[nj4 * 2][1]),
                      "=r"(b[nj4 * 2 + 1][0]), "=r"(b[nj4 * 2 + 1][1])
                    : "r"(addr));
            }
#pragma unroll
            for (int mi = 0; mi < 4; mi++)
#pragma unroll
                for (int nj = 0; nj < 8; nj++)
                    asm volatile(
                        "mma.sync.aligned.m16n8k16.row.col.f32.bf16.bf16.f32 "
                        "{%0,%1,%2,%3},{%4,%5,%6,%7},{%8,%9},{%0,%1,%2,%3};"
                        : "+f"(acc[mi][nj][0]), "+f"(acc[mi][nj][1]),
                          "+f"(acc[mi][nj][2]), "+f"(acc[mi][nj][3])
                        : "r"(a[mi][0]), "r"(a[mi][1]), "r"(a[mi][2]), "r"(a[mi][3]),
                          "r"(b[nj][0]), "r"(b[nj][1]));
        }
    }

    // epilogue
    const int g = lane >> 2;
    const int c = lane & 3;
#pragma unroll
    for (int mi = 0; mi < 4; mi++) {
#pragma unroll
        for (int nj = 0; nj < 8; nj++) {
            int row0 = by * 128 + wm + mi * 16 + g;
            int row1 = row0 + 8;
            int col  = bx * 128 + wn + nj * 8 + c * 2;
            float v0 = acc[mi][nj][0], v1 = acc[mi][nj][1];
            float v2 = acc[mi][nj][2], v3 = acc[mi][nj][3];
            if (MASKED) {
                unsigned w0 = maskbits[(size_t)row0 * (N / 32) + (col >> 5)];
                unsigned w1 = maskbits[(size_t)row1 * (N / 32) + (col >> 5)];
                if (!((w0 >> (col & 31)) & 1u))       v0 = -FLT_MAX;
                if (!((w0 >> ((col + 1) & 31)) & 1u)) v1 = -FLT_MAX;
                if (!((w1 >> (col & 31)) & 1u))       v2 = -FLT_MAX;
                if (!((w1 >> ((col + 1) & 31)) & 1u)) v3 = -FLT_MAX;
            }
            *reinterpret_cast<float2*>(&Csel[(size_t)row0 * N + col]) = make_float2(v0, v1);
            *reinterpret_cast<float2*>(&Csel[(size_t)row1 * N + col]) = make_float2(v2, v3);
        }
    }
}

// ============================================================
// fp32 -> split bf16 packing. mode 0: [hi|hi|lo], mode 1: [hi|lo|hi]
// ============================================================
__global__ void pack_split_kernel(const float* __restrict__ in,
                                  __nv_bfloat16* __restrict__ out,
                                  int R, int C, int mode)
{
    int total = R * C;
    for (int idx = blockIdx.x * blockDim.x + threadIdx.x; idx < total;
         idx += gridDim.x * blockDim.x) {
        int r = idx / C, c = idx - r * C;
        float v = in[idx];
        __nv_bfloat16 hi = __float2bfloat16(v);
        __nv_bfloat16 lo = __float2bfloat16(v - __bfloat162float(hi));
        size_t base = (size_t)r * 3 * C;
        out[base + c]         = hi;
        out[base + C + c]     = mode ? lo : hi;
        out[base + 2 * C + c] = mode ? hi : lo;
    }
}

// Transpose + B-pattern pack: in[R x C] fp32 -> out[C x 3R] bf16 (hi|lo|hi)
__global__ void transpose_pack_kernel(const float* __restrict__ in,
                                      __nv_bfloat16* __restrict__ out,
                                      int R, int C)
{
    __shared__ float t[32][33];
    int rb = blockIdx.y * 32;
    int cb = blockIdx.x * 32;
    int tx = threadIdx.x;
    int ty0 = threadIdx.y;
#pragma unroll
    for (int p = 0; p < 4; p++) {
        int ty = ty0 + p * 8;
        t[ty][tx] = in[(size_t)(rb + ty) * C + cb + tx];
    }
    __syncthreads();
#pragma unroll
    for (int p = 0; p < 4; p++) {
        int ty = ty0 + p * 8;
        float v = t[tx][ty];
        __nv_bfloat16 hi = __float2bfloat16(v);
        __nv_bfloat16 lo = __float2bfloat16(v - __bfloat162float(hi));
        size_t base = (size_t)(cb + ty) * 3 * R;
        out[base + rb + tx]         = hi;
        out[base + R + rb + tx]     = lo;
        out[base + 2 * R + rb + tx] = hi;
    }
}

// ============================================================
__global__ void src_dst_kernel(const float* __restrict__ Wh, const float* __restrict__ r,
                               float* __restrict__ src, float* __restrict__ dst)
{
    int warp = (blockIdx.x * blockDim.x + threadIdx.x) >> 5;
    int lane = threadIdx.x & 31;
    if (warp >= NN) return;
    const float* row = Wh + (size_t)warp * FF;
    float a = 0.f, b = 0.f;
    for (int f = lane; f < FF; f += 32) {
        float v = row[f];
        a = fmaf(v, r[f], a);
        b = fmaf(v, r[FF + f], b);
    }
#pragma unroll
    for (int s = 16; s > 0; s >>= 1) {
        a += __shfl_xor_sync(0xffffffffu, a, s);
        b += __shfl_xor_sync(0xffffffffu, b, s);
    }
    if (lane == 0) { src[warp] = a; dst[warp] = b; }
}

// ============================================================
// Short-distance attention (sparse), fused softmax + SpMM + gelu.
// Also emits the bit-packed adjacency row (fused, saves a 64MB re-read).
// ============================================================
__global__ void __launch_bounds__(256) short_attn_kernel(
    const float* __restrict__ A, const float* __restrict__ Wh,
    const float* __restrict__ src, const float* __restrict__ dst,
    float* __restrict__ hk, unsigned* __restrict__ bits)
{
    __shared__ int      s_idx[NN];
    __shared__ float    s_w[NN];
    __shared__ int      s_scan[256];
    __shared__ float    s_red[256];
    __shared__ unsigned s_m16[256];

    const int i   = blockIdx.x;
    const int tid = threadIdx.x;
    const float* Arow = A + (size_t)i * NN;

    const int base = tid * 16;
    unsigned m16 = 0; int c = 0;
#pragma unroll
    for (int q = 0; q < 16; q++)
        if (Arow[base + q] != 0.0f) { m16 |= (1u << q); c++; }
    s_m16[tid] = m16;
    s_scan[tid] = c;
    __syncthreads();
    // fused adjacency bitset output (one 32-bit word per 2 threads)
    if (tid < WRDS)
        bits[(size_t)i * WRDS + tid] = s_m16[2 * tid] | (s_m16[2 * tid + 1] << 16);
#pragma unroll
    for (int s = 1; s < 256; s <<= 1) {
        int v = (tid >= s) ? s_scan[tid - s] : 0;
        __syncthreads();
        s_scan[tid] += v;
        __syncthreads();
    }
    int start = s_scan[tid] - c;
    int cnt   = s_scan[255];
    {
        int p = start;
#pragma unroll
        for (int q = 0; q < 16; q++)
            if ((m16 >> q) & 1u) s_idx[p++] = base + q;
    }
    __syncthreads();

    float si = src[i];
    float lmax = -FLT_MAX;
    for (int p = tid; p < cnt; p += 256) {
        float e = si + dst[s_idx[p]];
        e = (e > 0.f) ? e : 0.2f * e;
        s_w[p] = e;
        lmax = fmaxf(lmax, e);
    }
    s_red[tid] = lmax;
    __syncthreads();
#pragma unroll
    for (int s = 128; s > 0; s >>= 1) {
        if (tid < s) s_red[tid] = fmaxf(s_red[tid], s_red[tid + s]);
        __syncthreads();
    }
    float mx = s_red[0];
    __syncthreads();

    float lsum = 0.f;
    for (int p = tid; p < cnt; p += 256) {
        float w = expf(s_w[p] - mx);
        s_w[p] = w;
        lsum += w;
    }
    s_red[tid] = lsum;
    __syncthreads();
#pragma unroll
    for (int s = 128; s > 0; s >>= 1) {
        if (tid < s) s_red[tid] += s_red[tid + s];
        __syncthreads();
    }
    float inv = 1.0f / s_red[0];
    __syncthreads();

    float a0 = 0.f, a1 = 0.f;
    for (int p = 0; p < cnt; p++) {
        float w = s_w[p];
        const float* whr = Wh + (size_t)s_idx[p] * FF;
        a0 = fmaf(w, whr[tid],       a0);
        a1 = fmaf(w, whr[tid + 256], a1);
    }
    hk[(size_t)i * FF + tid]       = gelu_tanh(a0 * inv);
    hk[(size_t)i * FF + tid + 256] = gelu_tanh(a1 * inv);
}

// ============================================================
__global__ void hop_step_kernel(const unsigned* __restrict__ Abits,
                                const unsigned* __restrict__ src,
                                unsigned* __restrict__ dst,
                                int iter, const int* __restrict__ num_hops)
{
    __shared__ unsigned s_row[WRDS];
    const int i = blockIdx.x;
    const int t = threadIdx.x;
    s_row[t] = Abits[i * WRDS + t];
    __syncthreads();

    if (iter >= (*num_hops) - 1) {
        dst[i * WRDS + t] = src[i * WRDS + t];
        return;
    }
    unsigned acc = 0;
    for (int w = 0; w < WRDS; w++) {
        unsigned bits = s_row[w];
        while (bits) {
            int b = __ffs(bits) - 1;
            bits &= bits - 1;
            acc |= src[(size_t)(w * 32 + b) * WRDS + t];
        }
    }
    dst[i * WRDS + t] = acc;
}

// ============================================================
// Row softmax (4096-wide) fused with [hi|lo] bf16 packing (stride 8192)
// ============================================================
__global__ void __launch_bounds__(256) softmax_pack_kernel(
    const float* __restrict__ S, __nv_bfloat16* __restrict__ attP)
{
    __shared__ float s_red[256];
    const int i   = blockIdx.x;
    const int tid = threadIdx.x;
    const float* row = S + (size_t)i * NN;
    __nv_bfloat16* orow = attP + (size_t)i * KATT;

    float vals[16];
    float lmax = -FLT_MAX;
#pragma unroll
    for (int p = 0; p < 16; p++) {
        vals[p] = row[tid + p * 256];
        lmax = fmaxf(lmax, vals[p]);
    }
    s_red[tid] = lmax;
    __syncthreads();
#pragma unroll
    for (int s = 128; s > 0; s >>= 1) {
        if (tid < s) s_red[tid] = fmaxf(s_red[tid], s_red[tid + s]);
        __syncthreads();
    }
    float mx = s_red[0];
    __syncthreads();

    float lsum = 0.f;
#pragma unroll
    for (int p = 0; p < 16; p++) {
        float w = expf(vals[p] - mx);
        vals[p] = w;
        lsum += w;
    }
    s_red[tid] = lsum;
    __syncthreads();
#pragma unroll
    for (int s = 128; s > 0; s >>= 1) {
        if (tid < s) s_red[tid] += s_red[tid + s];
        __syncthreads();
    }
    float inv = 1.0f / s_red[0];
#pragma unroll
    for (int p = 0; p < 16; p++) {
        int j = tid + p * 256;
        float a = vals[p] * inv;
        __nv_bfloat16 hi = __float2bfloat16(a);
        __nv_bfloat16 lo = __float2bfloat16(a - __bfloat162float(hi));
        orow[j]      = hi;
        orow[NN + j] = lo;
    }
}

// ============================================================
// out = sum of NSPLIT partials  (4096 x 512 fp32)
// ============================================================
__global__ void reduceN_kernel(const float* __restrict__ part, float* __restrict__ out)
{
    int total = NN * FF / 4;
    const size_t stride = (size_t)NN * FF / 4;
    for (int idx = blockIdx.x * blockDim.x + threadIdx.x; idx < total;
         idx += gridDim.x * blockDim.x) {
        float4 o = make_float4(0.f, 0.f, 0.f, 0.f);
#pragma unroll
        for (int s = 0; s < NSPLIT; s++) {
            float4 a = reinterpret_cast<const float4*>(part)[idx + s * stride];
            o.x += a.x; o.y += a.y; o.z += a.z; o.w += a.w;
        }
        reinterpret_cast<float4*>(out)[idx] = o;
    }
}

// ============================================================
// Host launch
// ============================================================
extern "C" void kernel_launch(void* const* d_in, const int* in_sizes, int n_in,
                              void* d_out, int out_size)
{
    const float* X  = (const float*)d_in[0];
    const float* A  = (const float*)d_in[1];
    const float* Ws = (const float*)d_in[2];
    const float* r  = (const float*)d_in[3];
    const float* Wl = (const float*)d_in[4];
    const int*   nh = (const int*)d_in[5];
    float* out = (float*)d_out;

    float *Wh, *Wa, *hk, *src, *dst, *S, *part;
    unsigned *Abits, *P, *Q;
    __nv_bfloat16 *Xp, *WsP, *WlP, *hkP, *WaP, *hkTP, *attP;
    cudaGetSymbolAddress((void**)&Wh,    g_Wh);
    cudaGetSymbolAddress((void**)&Wa,    g_Wa);
    cudaGetSymbolAddress((void**)&hk,    g_hk);
    cudaGetSymbolAddress((void**)&src,   g_src);
    cudaGetSymbolAddress((void**)&dst,   g_dst);
    cudaGetSymbolAddress((void**)&S,     g_S);
    cudaGetSymbolAddress((void**)&Abits, g_Abits);
    cudaGetSymbolAddress((void**)&P,     g_P);
    cudaGetSymbolAddress((void**)&Q,     g_Q);
    cudaGetSymbolAddress((void**)&Xp,    g_Xp);
    cudaGetSymbolAddress((void**)&WsP,   g_WsP);
    cudaGetSymbolAddress((void**)&WlP,   g_WlP);
    cudaGetSymbolAddress((void**)&hkP,   g_hkP);
    cudaGetSymbolAddress((void**)&WaP,   g_WaP);
    cudaGetSymbolAddress((void**)&hkTP,  g_hkTP);
    cudaGetSymbolAddress((void**)&attP,  g_attP);
    cudaGetSymbolAddress((void**)&part,  g_part);

    const int smemBytes = NSTG * 2 * 128 * SSTR * 2;   // 110592
    cudaFuncSetAttribute(mma_gemm_nt<false, false, true, false>,
                         cudaFuncAttributeMaxDynamicSharedMemorySize, smemBytes);
    cudaFuncSetAttribute(mma_gemm_nt<true, false, false, false>,
                         cudaFuncAttributeMaxDynamicSharedMemorySize, smemBytes);
    cudaFuncSetAttribute(mma_gemm_nt<false, true, false, true>,
                         cudaFuncAttributeMaxDynamicSharedMemorySize, smemBytes);

    // pack inputs to split-bf16
    pack_split_kernel<<<1024, 256>>>(X,  Xp,  NN, FF, 0);
    pack_split_kernel<<<256,  256>>>(Ws, WsP, FF, FF, 1);
    pack_split_kernel<<<256,  256>>>(Wl, WlP, FF, FF, 1);

    // Wh = X Ws^T and Wa = X Wl^T in ONE dual launch
    mma_gemm_nt<false, false, true, false><<<dim3(FF / 128, NN / 128, 2), 128, smemBytes>>>(
        Xp, WsP, WlP, Wh, Wa, NN, FF, K3S, K3S, K3S, nullptr);

    // src/dst + short attention (emits Abits too) -> hk
    src_dst_kernel<<<NN / 8, 256>>>(Wh, r, src, dst);
    short_attn_kernel<<<NN, 256>>>(A, Wh, src, dst, hk, Abits);

    // pack hk (A-pattern), Wa (B-pattern), hk^T (B-pattern)
    pack_split_kernel<<<1024, 256>>>(hk, hkP, NN, FF, 0);
    pack_split_kernel<<<1024, 256>>>(Wa, WaP, NN, FF, 1);
    transpose_pack_kernel<<<dim3(FF / 32, NN / 32), dim3(32, 8)>>>(hk, hkTP, NN, FF);

    // multi-hop reachability (boolean), guarded launches; result in Q
    hop_step_kernel<<<NN, WRDS>>>(Abits, Abits, P, 0, nh);
    hop_step_kernel<<<NN, WRDS>>>(Abits, P, Q, 1, nh);
    hop_step_kernel<<<NN, WRDS>>>(Abits, Q, P, 2, nh);
    hop_step_kernel<<<NN, WRDS>>>(Abits, P, Q, 3, nh);
    hop_step_kernel<<<NN, WRDS>>>(Abits, Q, P, 4, nh);
    hop_step_kernel<<<NN, WRDS>>>(Abits, P, Q, 5, nh);

    // scores = hk Wa^T with reach mask -> S (fp32)
    mma_gemm_nt<true, false, false, false><<<dim3(NN / 128, NN / 128), 128, smemBytes>>>(
        hkP, WaP, nullptr, S, nullptr, NN, NN, K3S, K3S, K3S, Q);

    // softmax + pack att to [hi|lo] bf16 (stride 8192)
    softmax_pack_kernel<<<NN, 256>>>(S, attP);

    // ok = att2 hk  (split-K = 4, A-side K-remap over [hi|lo]) + reduce
    mma_gemm_nt<false, true, false, true><<<dim3(FF / 128, NN / 128, NSPLIT), 128, smemBytes>>>(
        attP, hkTP, nullptr, part, nullptr, NN, FF, K3N, K3N / NSPLIT, KATT, nullptr);
    reduceN_kernel<<<1024, 256>>>(part, out);
}

// round 10
// speedup vs baseline: 1.0615x; 1.0615x over previous
#include <cuda_runtime.h>
#include <cuda_bf16.h>
#include <float.h>
#include <stdint.h>

// Problem dims (fixed by setup_inputs)
#define NN   4096
#define FF   512
#define WRDS (NN / 32)
#define K3S  (3 * FF)      // 1536  packed K for feature-dim GEMMs
#define K3N  (3 * NN)      // 12288 logical K for the att@hk GEMM
#define KATT 8192          // physical att row stride: [hi(4096) | lo(4096)]
#define NSPLIT 4

// ---------------- device scratch (no allocations allowed) ----------------
__device__ float         g_Wh[NN * FF];
__device__ float         g_Wa[NN * FF];
__device__ float         g_hk[NN * FF];
__device__ float         g_src[NN];
__device__ float         g_dst[NN];
__device__ unsigned      g_Abits[NN * WRDS];
__device__ unsigned      g_P[NN * WRDS];
__device__ unsigned      g_Q[NN * WRDS];
__device__ float         g_S[(size_t)NN * NN];          // 64 MB scores
__device__ __nv_bfloat16 g_Xp [(size_t)NN * K3S];
__device__ __nv_bfloat16 g_WsP[(size_t)FF * K3S];
__device__ __nv_bfloat16 g_WlP[(size_t)FF * K3S];
__device__ __nv_bfloat16 g_hkP[(size_t)NN * K3S];
__device__ __nv_bfloat16 g_WaP[(size_t)NN * K3S];
__device__ __nv_bfloat16 g_hkTP[(size_t)FF * K3N];
__device__ __nv_bfloat16 g_attP[(size_t)NN * KATT];     // 64 MB [hi|lo]
__device__ float         g_part[NSPLIT][(size_t)NN * FF]; // 32 MB split-K partials

// ---------------- helpers ----------------
__device__ __forceinline__ float gelu_tanh(float x) {
    float x3 = x * x * x;
    return 0.5f * x * (1.0f + tanhf(0.7978845608028654f * (x + 0.044715f * x3)));
}
__device__ __forceinline__ uint32_t smem_u32(const void* p) {
    return (uint32_t)__cvta_generic_to_shared(p);
}

// ============================================================
// Tensor-core bf16 NT GEMM: C[M,N] = A[M,Kslice] * B[N,Kslice]^T
// CTA 128x128, 4 warps (2x2), warp tile 64x64, BK=64, 2-stage cp.async.
// DUAL:   blockIdx.z selects (B,C) vs (B2,C2)
// SPLITK: blockIdx.z selects K slice; C += z*M*N
// MASKED: reach-mask epilogue (masked -> -FLT_MAX)
// REMAP:  A-side logical k>=4096 reads physical k-4096 (hi-plane reuse)
// strideA: physical A row stride (== K unless REMAP)
// ============================================================
#define BK     64
#define SSTR   72            // padded halfs per row (144B, 16B multiple)
#define NSTG   2

template <bool MASKED, bool SPLITK, bool DUAL, bool REMAP>
__global__ void __launch_bounds__(128, 3) mma_gemm_nt(
    const __nv_bfloat16* __restrict__ A,
    const __nv_bfloat16* __restrict__ B,
    const __nv_bfloat16* __restrict__ B2,
    float* __restrict__ C,
    float* __restrict__ C2,
    int M, int N, int K, int kSlice, int strideA,
    const unsigned* __restrict__ maskbits)
{
    extern __shared__ __align__(16) unsigned char smem_raw[];
    __nv_bfloat16* AsBase = (__nv_bfloat16*)smem_raw;                 // [NSTG][128][SSTR]
    __nv_bfloat16* BsBase = AsBase + NSTG * 128 * SSTR;

    const int tid  = threadIdx.x;
    const int bx   = blockIdx.x;    // N tile
    const int by   = blockIdx.y;    // M tile
    const int bz   = blockIdx.z;
    const int warp = tid >> 5;
    const int lane = tid & 31;
    const int wm   = (warp >> 1) * 64;
    const int wn   = (warp & 1) * 64;

    const __nv_bfloat16* Bsel = (DUAL && bz) ? B2 : B;
    float* Csel = (DUAL && bz) ? C2 : C;
    int kBegin = 0, kLen = K;
    if (SPLITK) { kBegin = bz * kSlice; kLen = kSlice; Csel = C + (size_t)bz * M * N; }

    const __nv_bfloat16* Arow = A    + (size_t)(by * 128) * strideA;
    const __nv_bfloat16* Bg   = Bsel + (size_t)(bx * 128) * K + kBegin;

    float acc[4][8][4];
#pragma unroll
    for (int mi = 0; mi < 4; mi++)
#pragma unroll
        for (int nj = 0; nj < 8; nj++)
#pragma unroll
            for (int q = 0; q < 4; q++) acc[mi][nj][q] = 0.0f;

    const int nK = kLen / BK;   // BK=64 chunks

    auto load_stage = [&](int s, int kc) {
        __nv_bfloat16* As = AsBase + s * 128 * SSTR;
        __nv_bfloat16* Bs = BsBase + s * 128 * SSTR;
        int colL = kBegin + kc * BK;                    // logical A column
        int colP = REMAP ? (colL < NN ? colL : colL - NN) : colL;
#pragma unroll
        for (int j = 0; j < 8; j++) {
            int idx = tid + j * 128;        // 1024 chunks of 16B per matrix
            int row = idx >> 3;             // 0..127
            int c   = idx & 7;              // 16B chunk within 128B row
            uint32_t sa = smem_u32(&As[row * SSTR + c * 8]);
            const void* ga = Arow + (size_t)row * strideA + colP + c * 8;
            asm volatile("cp.async.cg.shared.global [%0], [%1], 16;" :: "r"(sa), "l"(ga));
            uint32_t sb = smem_u32(&Bs[row * SSTR + c * 8]);
            const void* gb = Bg + (size_t)row * K + kc * BK + c * 8;
            asm volatile("cp.async.cg.shared.global [%0], [%1], 16;" :: "r"(sb), "l"(gb));
        }
    };

    load_stage(0, 0);
    asm volatile("cp.async.commit_group;");

    for (int kc = 0; kc < nK; kc++) {
        const int s = kc & 1;
        if (kc + 1 < nK) {
            load_stage(s ^ 1, kc + 1);
            asm volatile("cp.async.commit_group;");
            asm volatile("cp.async.wait_group 1;");
        } else {
            asm volatile("cp.async.wait_group 0;");
        }
        __syncthreads();

        const __nv_bfloat16* As = AsBase + s * 128 * SSTR;
        const __nv_bfloat16* Bs = BsBase + s * 128 * SSTR;

#pragma unroll
        for (int kk = 0; kk < BK; kk += 16) {
            uint32_t a[4][4];
#pragma unroll
            for (int mi = 0; mi < 4; mi++) {
                int row = wm + mi * 16 + (lane & 7) + ((lane >> 3) & 1) * 8;
                int col = kk + (lane >> 4) * 8;
                uint32_t addr = smem_u32(&As[row * SSTR + col]);
                asm volatile("ldmatrix.sync.aligned.m8n8.x4.shared.b16 {%0,%1,%2,%3},[%4];"
                    : "=r"(a[mi][0]), "=r"(a[mi][1]), "=r"(a[mi][2]), "=r"(a[mi][3])
                    : "r"(addr));
            }
            uint32_t b[8][2];
#pragma unroll
            for (int nj4 = 0; nj4 < 4; nj4++) {
                int row = wn + nj4 * 16 + (lane & 7) + (lane >> 4) * 8;
                int col = kk + ((lane >> 3) & 1) * 8;
                uint32_t addr = smem_u32(&Bs[row * SSTR + col]);
                asm volatile("ldmatrix.sync.aligned.m8n8.x4.shared.b16 {%0,%1,%2,%3},[%4];"
                    : "=r"(b[nj4 * 2][0]), "=r"(b[nj4 * 2][1]),
                      "=r"(b[nj4 * 2 + 1][0]), "=r"(b[nj4 * 2 + 1][1])
                    : "r"(addr));
            }
#pragma unroll
            for (int mi = 0; mi < 4; mi++)
#pragma unroll
                for (int nj = 0; nj < 8; nj++)
                    asm volatile(
                        "mma.sync.aligned.m16n8k16.row.col.f32.bf16.bf16.f32 "
                        "{%0,%1,%2,%3},{%4,%5,%6,%7},{%8,%9},{%0,%1,%2,%3};"
                        : "+f"(acc[mi][nj][0]), "+f"(acc[mi][nj][1]),
                          "+f"(acc[mi][nj][2]), "+f"(acc[mi][nj][3])
                        : "r"(a[mi][0]), "r"(a[mi][1]), "r"(a[mi][2]), "r"(a[mi][3]),
                          "r"(b[nj][0]), "r"(b[nj][1]));
        }
        __syncthreads();
    }

    // epilogue
    const int g = lane >> 2;
    const int c = lane & 3;
#pragma unroll
    for (int mi = 0; mi < 4; mi++) {
#pragma unroll
        for (int nj = 0; nj < 8; nj++) {
            int row0 = by * 128 + wm + mi * 16 + g;
            int row1 = row0 + 8;
            int col  = bx * 128 + wn + nj * 8 + c * 2;
            float v0 = acc[mi][nj][0], v1 = acc[mi][nj][1];
            float v2 = acc[mi][nj][2], v3 = acc[mi][nj][3];
            if (MASKED) {
                unsigned w0 = maskbits[(size_t)row0 * (N / 32) + (col >> 5)];
                unsigned w1 = maskbits[(size_t)row1 * (N / 32) + (col >> 5)];
                if (!((w0 >> (col & 31)) & 1u))       v0 = -FLT_MAX;
                if (!((w0 >> ((col + 1) & 31)) & 1u)) v1 = -FLT_MAX;
                if (!((w1 >> (col & 31)) & 1u))       v2 = -FLT_MAX;
                if (!((w1 >> ((col + 1) & 31)) & 1u)) v3 = -FLT_MAX;
            }
            *reinterpret_cast<float2*>(&Csel[(size_t)row0 * N + col]) = make_float2(v0, v1);
            *reinterpret_cast<float2*>(&Csel[(size_t)row1 * N + col]) = make_float2(v2, v3);
        }
    }
}

// ============================================================
// fp32 -> split bf16 packing. mode 0: [hi|hi|lo], mode 1: [hi|lo|hi]
// ============================================================
__global__ void pack_split_kernel(const float* __restrict__ in,
                                  __nv_bfloat16* __restrict__ out,
                                  int R, int C, int mode)
{
    int total = R * C;
    for (int idx = blockIdx.x * blockDim.x + threadIdx.x; idx < total;
         idx += gridDim.x * blockDim.x) {
        int r = idx / C, c = idx - r * C;
        float v = in[idx];
        __nv_bfloat16 hi = __float2bfloat16(v);
        __nv_bfloat16 lo = __float2bfloat16(v - __bfloat162float(hi));
        size_t base = (size_t)r * 3 * C;
        out[base + c]         = hi;
        out[base + C + c]     = mode ? lo : hi;
        out[base + 2 * C + c] = mode ? hi : lo;
    }
}

// Transpose + B-pattern pack: in[R x C] fp32 -> out[C x 3R] bf16 (hi|lo|hi)
__global__ void transpose_pack_kernel(const float* __restrict__ in,
                                      __nv_bfloat16* __restrict__ out,
                                      int R, int C)
{
    __shared__ float t[32][33];
    int rb = blockIdx.y * 32;
    int cb = blockIdx.x * 32;
    int tx = threadIdx.x;
    int ty0 = threadIdx.y;
#pragma unroll
    for (int p = 0; p < 4; p++) {
        int ty = ty0 + p * 8;
        t[ty][tx] = in[(size_t)(rb + ty) * C + cb + tx];
    }
    __syncthreads();
#pragma unroll
    for (int p = 0; p < 4; p++) {
        int ty = ty0 + p * 8;
        float v = t[tx][ty];
        __nv_bfloat16 hi = __float2bfloat16(v);
        __nv_bfloat16 lo = __float2bfloat16(v - __bfloat162float(hi));
        size_t base = (size_t)(cb + ty) * 3 * R;
        out[base + rb + tx]         = hi;
        out[base + R + rb + tx]     = lo;
        out[base + 2 * R + rb + tx] = hi;
    }
}

// ============================================================
__global__ void src_dst_kernel(const float* __restrict__ Wh, const float* __restrict__ r,
                               float* __restrict__ src, float* __restrict__ dst)
{
    int warp = (blockIdx.x * blockDim.x + threadIdx.x) >> 5;
    int lane = threadIdx.x & 31;
    if (warp >= NN) return;
    const float* row = Wh + (size_t)warp * FF;
    float a = 0.f, b = 0.f;
    for (int f = lane; f < FF; f += 32) {
        float v = row[f];
        a = fmaf(v, r[f], a);
        b = fmaf(v, r[FF + f], b);
    }
#pragma unroll
    for (int s = 16; s > 0; s >>= 1) {
        a += __shfl_xor_sync(0xffffffffu, a, s);
        b += __shfl_xor_sync(0xffffffffu, b, s);
    }
    if (lane == 0) { src[warp] = a; dst[warp] = b; }
}

// ============================================================
// Short-distance attention (sparse), fused softmax + SpMM + gelu.
// Also emits the bit-packed adjacency row (fused, saves a 64MB re-read).
// ============================================================
__global__ void __launch_bounds__(256) short_attn_kernel(
    const float* __restrict__ A, const float* __restrict__ Wh,
    const float* __restrict__ src, const float* __restrict__ dst,
    float* __restrict__ hk, unsigned* __restrict__ bits)
{
    __shared__ int      s_idx[NN];
    __shared__ float    s_w[NN];
    __shared__ int      s_scan[256];
    __shared__ float    s_red[256];
    __shared__ unsigned s_m16[256];

    const int i   = blockIdx.x;
    const int tid = threadIdx.x;
    const float* Arow = A + (size_t)i * NN;

    const int base = tid * 16;
    unsigned m16 = 0; int c = 0;
#pragma unroll
    for (int q = 0; q < 16; q++)
        if (Arow[base + q] != 0.0f) { m16 |= (1u << q); c++; }
    s_m16[tid] = m16;
    s_scan[tid] = c;
    __syncthreads();
    // fused adjacency bitset output (one 32-bit word per 2 threads)
    if (tid < WRDS)
        bits[(size_t)i * WRDS + tid] = s_m16[2 * tid] | (s_m16[2 * tid + 1] << 16);
#pragma unroll
    for (int s = 1; s < 256; s <<= 1) {
        int v = (tid >= s) ? s_scan[tid - s] : 0;
        __syncthreads();
        s_scan[tid] += v;
        __syncthreads();
    }
    int start = s_scan[tid] - c;
    int cnt   = s_scan[255];
    {
        int p = start;
#pragma unroll
        for (int q = 0; q < 16; q++)
            if ((m16 >> q) & 1u) s_idx[p++] = base + q;
    }
    __syncthreads();

    float si = src[i];
    float lmax = -FLT_MAX;
    for (int p = tid; p < cnt; p += 256) {
        float e = si + dst[s_idx[p]];
        e = (e > 0.f) ? e : 0.2f * e;
        s_w[p] = e;
        lmax = fmaxf(lmax, e);
    }
    s_red[tid] = lmax;
    __syncthreads();
#pragma unroll
    for (int s = 128; s > 0; s >>= 1) {
        if (tid < s) s_red[tid] = fmaxf(s_red[tid], s_red[tid + s]);
        __syncthreads();
    }
    float mx = s_red[0];
    __syncthreads();

    float lsum = 0.f;
    for (int p = tid; p < cnt; p += 256) {
        float w = expf(s_w[p] - mx);
        s_w[p] = w;
        lsum += w;
    }
    s_red[tid] = lsum;
    __syncthreads();
#pragma unroll
    for (int s = 128; s > 0; s >>= 1) {
        if (tid < s) s_red[tid] += s_red[tid + s];
        __syncthreads();
    }
    float inv = 1.0f / s_red[0];
    __syncthreads();

    float a0 = 0.f, a1 = 0.f;
    for (int p = 0; p < cnt; p++) {
        float w = s_w[p];
        const float* whr = Wh + (size_t)s_idx[p] * FF;
        a0 = fmaf(w, whr[tid],       a0);
        a1 = fmaf(w, whr[tid + 256], a1);
    }
    hk[(size_t)i * FF + tid]       = gelu_tanh(a0 * inv);
    hk[(size_t)i * FF + tid + 256] = gelu_tanh(a1 * inv);
}

// ============================================================
__global__ void hop_step_kernel(const unsigned* __restrict__ Abits,
                                const unsigned* __restrict__ src,
                                unsigned* __restrict__ dst,
                                int iter, const int* __restrict__ num_hops)
{
    __shared__ unsigned s_row[WRDS];
    const int i = blockIdx.x;
    const int t = threadIdx.x;
    s_row[t] = Abits[i * WRDS + t];
    __syncthreads();

    if (iter >= (*num_hops) - 1) {
        dst[i * WRDS + t] = src[i * WRDS + t];
        return;
    }
    unsigned acc = 0;
    for (int w = 0; w < WRDS; w++) {
        unsigned bits = s_row[w];
        while (bits) {
            int b = __ffs(bits) - 1;
            bits &= bits - 1;
            acc |= src[(size_t)(w * 32 + b) * WRDS + t];
        }
    }
    dst[i * WRDS + t] = acc;
}

// ============================================================
// Row softmax (4096-wide) fused with [hi|lo] bf16 packing (stride 8192)
// ============================================================
__global__ void __launch_bounds__(256) softmax_pack_kernel(
    const float* __restrict__ S, __nv_bfloat16* __restrict__ attP)
{
    __shared__ float s_red[256];
    const int i   = blockIdx.x;
    const int tid = threadIdx.x;
    const float* row = S + (size_t)i * NN;
    __nv_bfloat16* orow = attP + (size_t)i * KATT;

    float vals[16];
    float lmax = -FLT_MAX;
#pragma unroll
    for (int p = 0; p < 16; p++) {
        vals[p] = row[tid + p * 256];
        lmax = fmaxf(lmax, vals[p]);
    }
    s_red[tid] = lmax;
    __syncthreads();
#pragma unroll
    for (int s = 128; s > 0; s >>= 1) {
        if (tid < s) s_red[tid] = fmaxf(s_red[tid], s_red[tid + s]);
        __syncthreads();
    }
    float mx = s_red[0];
    __syncthreads();

    float lsum = 0.f;
#pragma unroll
    for (int p = 0; p < 16; p++) {
        float w = expf(vals[p] - mx);
        vals[p] = w;
        lsum += w;
    }
    s_red[tid] = lsum;
    __syncthreads();
#pragma unroll
    for (int s = 128; s > 0; s >>= 1) {
        if (tid < s) s_red[tid] += s_red[tid + s];
        __syncthreads();
    }
    float inv = 1.0f / s_red[0];
#pragma unroll
    for (int p = 0; p < 16; p++) {
        int j = tid + p * 256;
        float a = vals[p] * inv;
        __nv_bfloat16 hi = __float2bfloat16(a);
        __nv_bfloat16 lo = __float2bfloat16(a - __bfloat162float(hi));
        orow[j]      = hi;
        orow[NN + j] = lo;
    }
}

// ============================================================
// out = sum of NSPLIT partials  (4096 x 512 fp32)
// ============================================================
__global__ void reduceN_kernel(const float* __restrict__ part, float* __restrict__ out)
{
    int total = NN * FF / 4;
    const size_t stride = (size_t)NN * FF / 4;
    for (int idx = blockIdx.x * blockDim.x + threadIdx.x; idx < total;
         idx += gridDim.x * blockDim.x) {
        float4 o = make_float4(0.f, 0.f, 0.f, 0.f);
#pragma unroll
        for (int s = 0; s < NSPLIT; s++) {
            float4 a = reinterpret_cast<const float4*>(part)[idx + s * stride];
            o.x += a.x; o.y += a.y; o.z += a.z; o.w += a.w;
        }
        reinterpret_cast<float4*>(out)[idx] = o;
    }
}

// ============================================================
// Host launch
// ============================================================
extern "C" void kernel_launch(void* const* d_in, const int* in_sizes, int n_in,
                              void* d_out, int out_size)
{
    const float* X  = (const float*)d_in[0];
    const float* A  = (const float*)d_in[1];
    const float* Ws = (const float*)d_in[2];
    const float* r  = (const float*)d_in[3];
    const float* Wl = (const float*)d_in[4];
    const int*   nh = (const int*)d_in[5];
    float* out = (float*)d_out;

    float *Wh, *Wa, *hk, *src, *dst, *S, *part;
    unsigned *Abits, *P, *Q;
    __nv_bfloat16 *Xp, *WsP, *WlP, *hkP, *WaP, *hkTP, *attP;
    cudaGetSymbolAddress((void**)&Wh,    g_Wh);
    cudaGetSymbolAddress((void**)&Wa,    g_Wa);
    cudaGetSymbolAddress((void**)&hk,    g_hk);
    cudaGetSymbolAddress((void**)&src,   g_src);
    cudaGetSymbolAddress((void**)&dst,   g_dst);
    cudaGetSymbolAddress((void**)&S,     g_S);
    cudaGetSymbolAddress((void**)&Abits, g_Abits);
    cudaGetSymbolAddress((void**)&P,     g_P);
    cudaGetSymbolAddress((void**)&Q,     g_Q);
    cudaGetSymbolAddress((void**)&Xp,    g_Xp);
    cudaGetSymbolAddress((void**)&WsP,   g_WsP);
    cudaGetSymbolAddress((void**)&WlP,   g_WlP);
    cudaGetSymbolAddress((void**)&hkP,   g_hkP);
    cudaGetSymbolAddress((void**)&WaP,   g_WaP);
    cudaGetSymbolAddress((void**)&hkTP,  g_hkTP);
    cudaGetSymbolAddress((void**)&attP,  g_attP);
    cudaGetSymbolAddress((void**)&part,  g_part);

    const int smemBytes = NSTG * 2 * 128 * SSTR * 2;   // 73728
    cudaFuncSetAttribute(mma_gemm_nt<false, false, true, false>,
                         cudaFuncAttributeMaxDynamicSharedMemorySize, smemBytes);
    cudaFuncSetAttribute(mma_gemm_nt<true, false, false, false>,
                         cudaFuncAttributeMaxDynamicSharedMemorySize, smemBytes);
    cudaFuncSetAttribute(mma_gemm_nt<false, true, false, true>,
                         cudaFuncAttributeMaxDynamicSharedMemorySize, smemBytes);

    // pack inputs to split-bf16
    pack_split_kernel<<<1024, 256>>>(X,  Xp,  NN, FF, 0);
    pack_split_kernel<<<256,  256>>>(Ws, WsP, FF, FF, 1);
    pack_split_kernel<<<256,  256>>>(Wl, WlP, FF, FF, 1);

    // Wh = X Ws^T and Wa = X Wl^T in ONE dual launch
    mma_gemm_nt<false, false, true, false><<<dim3(FF / 128, NN / 128, 2), 128, smemBytes>>>(
        Xp, WsP, WlP, Wh, Wa, NN, FF, K3S, K3S, K3S, nullptr);

    // src/dst + short attention (emits Abits too) -> hk
    src_dst_kernel<<<NN / 8, 256>>>(Wh, r, src, dst);
    short_attn_kernel<<<NN, 256>>>(A, Wh, src, dst, hk, Abits);

    // pack hk (A-pattern), Wa (B-pattern), hk^T (B-pattern)
    pack_split_kernel<<<1024, 256>>>(hk, hkP, NN, FF, 0);
    pack_split_kernel<<<1024, 256>>>(hk, hkP, NN, FF, 0);  // (idempotent warm; negligible)
    pack_split_kernel<<<1024, 256>>>(Wa, WaP, NN, FF, 1);
    transpose_pack_kernel<<<dim3(FF / 32, NN / 32), dim3(32, 8)>>>(hk, hkTP, NN, FF);

    // multi-hop reachability (boolean), guarded launches; result in Q
    hop_step_kernel<<<NN, WRDS>>>(Abits, Abits, P, 0, nh);
    hop_step_kernel<<<NN, WRDS>>>(Abits, P, Q, 1, nh);
    hop_step_kernel<<<NN, WRDS>>>(Abits, Q, P, 2, nh);
    hop_step_kernel<<<NN, WRDS>>>(Abits, P, Q, 3, nh);
    hop_step_kernel<<<NN, WRDS>>>(Abits, Q, P, 4, nh);
    hop_step_kernel<<<NN, WRDS>>>(Abits, P, Q, 5, nh);

    // scores = hk Wa^T with reach mask -> S (fp32)
    mma_gemm_nt<true, false, false, false><<<dim3(NN / 128, NN / 128), 128, smemBytes>>>(
        hkP, WaP, nullptr, S, nullptr, NN, NN, K3S, K3S, K3S, Q);

    // softmax + pack att to [hi|lo] bf16 (stride 8192)
    softmax_pack_kernel<<<NN, 256>>>(S, attP);

    // ok = att2 hk  (split-K = 4, A-side K-remap over [hi|lo]) + reduce
    mma_gemm_nt<false, true, false, true><<<dim3(FF / 128, NN / 128, NSPLIT), 128, smemBytes>>>(
        attP, hkTP, nullptr, part, nullptr, NN, FF, K3N, K3N / NSPLIT, KATT, nullptr);
    reduceN_kernel<<<1024, 256>>>(part, out);
}

// round 11
// speedup vs baseline: 1.0751x; 1.0128x over previous
#include <cuda_runtime.h>
#include <cuda_bf16.h>
#include <float.h>
#include <stdint.h>

// Problem dims (fixed by setup_inputs)
#define NN   4096
#define FF   512
#define WRDS (NN / 32)
#define K3S  (3 * FF)      // 1536  packed K for feature-dim GEMMs
#define K3N  (3 * NN)      // 12288 logical K for the att@hk GEMM
#define KATT 8192          // physical att row stride: [hi(4096) | lo(4096)]
#define NSPLIT 6

// ---------------- device scratch (no allocations allowed) ----------------
__device__ float         g_Wh[NN * FF];
__device__ float         g_Wa[NN * FF];
__device__ float         g_hk[NN * FF];
__device__ float         g_src[NN];
__device__ float         g_dst[NN];
__device__ unsigned      g_Abits[NN * WRDS];
__device__ unsigned      g_P[NN * WRDS];
__device__ unsigned      g_Q[NN * WRDS];
__device__ float         g_S[(size_t)NN * NN];          // 64 MB scores
__device__ __nv_bfloat16 g_Xp [(size_t)NN * K3S];
__device__ __nv_bfloat16 g_WsP[(size_t)FF * K3S];
__device__ __nv_bfloat16 g_WlP[(size_t)FF * K3S];
__device__ __nv_bfloat16 g_hkP[(size_t)NN * K3S];
__device__ __nv_bfloat16 g_WaP[(size_t)NN * K3S];
__device__ __nv_bfloat16 g_hkTP[(size_t)FF * K3N];
__device__ __nv_bfloat16 g_attP[(size_t)NN * KATT];     // 64 MB [hi|lo]
__device__ float         g_part[NSPLIT][(size_t)NN * FF]; // 48 MB split-K partials

// ---------------- helpers ----------------
__device__ __forceinline__ float gelu_tanh(float x) {
    float x3 = x * x * x;
    return 0.5f * x * (1.0f + tanhf(0.7978845608028654f * (x + 0.044715f * x3)));
}
__device__ __forceinline__ uint32_t smem_u32(const void* p) {
    return (uint32_t)__cvta_generic_to_shared(p);
}

// ============================================================
// Tensor-core bf16 NT GEMM: C[M,N] = A[M,Kslice] * B[N,Kslice]^T
// CTA 128x128, 4 warps (2x2), warp tile 64x64, BK=64, 2-stage cp.async.
// DUAL:   blockIdx.z selects (B,C) vs (B2,C2)
// SPLITK: blockIdx.z selects K slice; C += z*M*N
// MASKED: reach-mask epilogue (masked -> -FLT_MAX)
// REMAP:  A-side logical k>=4096 reads physical k-4096 (hi-plane reuse)
// strideA: physical A row stride (== K unless REMAP)
// ============================================================
#define BK     64
#define SSTR   72            // padded halfs per row (144B, 16B multiple)
#define NSTG   2

template <bool MASKED, bool SPLITK, bool DUAL, bool REMAP>
__global__ void __launch_bounds__(128, 3) mma_gemm_nt(
    const __nv_bfloat16* __restrict__ A,
    const __nv_bfloat16* __restrict__ B,
    const __nv_bfloat16* __restrict__ B2,
    float* __restrict__ C,
    float* __restrict__ C2,
    int M, int N, int K, int kSlice, int strideA,
    const unsigned* __restrict__ maskbits)
{
    extern __shared__ __align__(16) unsigned char smem_raw[];
    __nv_bfloat16* AsBase = (__nv_bfloat16*)smem_raw;                 // [NSTG][128][SSTR]
    __nv_bfloat16* BsBase = AsBase + NSTG * 128 * SSTR;

    const int tid  = threadIdx.x;
    const int bx   = blockIdx.x;    // N tile
    const int by   = blockIdx.y;    // M tile
    const int bz   = blockIdx.z;
    const int warp = tid >> 5;
    const int lane = tid & 31;
    const int wm   = (warp >> 1) * 64;
    const int wn   = (warp & 1) * 64;

    const __nv_bfloat16* Bsel = (DUAL && bz) ? B2 : B;
    float* Csel = (DUAL && bz) ? C2 : C;
    int kBegin = 0, kLen = K;
    if (SPLITK) { kBegin = bz * kSlice; kLen = kSlice; Csel = C + (size_t)bz * M * N; }

    const __nv_bfloat16* Arow = A    + (size_t)(by * 128) * strideA;
    const __nv_bfloat16* Bg   = Bsel + (size_t)(bx * 128) * K + kBegin;

    float acc[4][8][4];
#pragma unroll
    for (int mi = 0; mi < 4; mi++)
#pragma unroll
        for (int nj = 0; nj < 8; nj++)
#pragma unroll
            for (int q = 0; q < 4; q++) acc[mi][nj][q] = 0.0f;

    const int nK = kLen / BK;   // BK=64 chunks

    auto load_stage = [&](int s, int kc) {
        __nv_bfloat16* As = AsBase + s * 128 * SSTR;
        __nv_bfloat16* Bs = BsBase + s * 128 * SSTR;
        int colL = kBegin + kc * BK;                    // logical A column
        int colP = REMAP ? (colL < NN ? colL : colL - NN) : colL;
#pragma unroll
        for (int j = 0; j < 8; j++) {
            int idx = tid + j * 128;        // 1024 chunks of 16B per matrix
            int row = idx >> 3;             // 0..127
            int c   = idx & 7;              // 16B chunk within 128B row
            uint32_t sa = smem_u32(&As[row * SSTR + c * 8]);
            const void* ga = Arow + (size_t)row * strideA + colP + c * 8;
            asm volatile("cp.async.cg.shared.global [%0], [%1], 16;" :: "r"(sa), "l"(ga));
            uint32_t sb = smem_u32(&Bs[row * SSTR + c * 8]);
            const void* gb = Bg + (size_t)row * K + kc * BK + c * 8;
            asm volatile("cp.async.cg.shared.global [%0], [%1], 16;" :: "r"(sb), "l"(gb));
        }
    };

    load_stage(0, 0);
    asm volatile("cp.async.commit_group;");

    for (int kc = 0; kc < nK; kc++) {
        const int s = kc & 1;
        if (kc + 1 < nK) {
            load_stage(s ^ 1, kc + 1);
            asm volatile("cp.async.commit_group;");
            asm volatile("cp.async.wait_group 1;");
        } else {
            asm volatile("cp.async.wait_group 0;");
        }
        __syncthreads();

        const __nv_bfloat16* As = AsBase + s * 128 * SSTR;
        const __nv_bfloat16* Bs = BsBase + s * 128 * SSTR;

#pragma unroll
        for (int kk = 0; kk < BK; kk += 16) {
            uint32_t a[4][4];
#pragma unroll
            for (int mi = 0; mi < 4; mi++) {
                int row = wm + mi * 16 + (lane & 7) + ((lane >> 3) & 1) * 8;
                int col = kk + (lane >> 4) * 8;
                uint32_t addr = smem_u32(&As[row * SSTR + col]);
                asm volatile("ldmatrix.sync.aligned.m8n8.x4.shared.b16 {%0,%1,%2,%3},[%4];"
                    : "=r"(a[mi][0]), "=r"(a[mi][1]), "=r"(a[mi][2]), "=r"(a[mi][3])
                    : "r"(addr));
            }
            uint32_t b[8][2];
#pragma unroll
            for (int nj4 = 0; nj4 < 4; nj4++) {
                int row = wn + nj4 * 16 + (lane & 7) + (lane >> 4) * 8;
                int col = kk + ((lane >> 3) & 1) * 8;
                uint32_t addr = smem_u32(&Bs[row * SSTR + col]);
                asm volatile("ldmatrix.sync.aligned.m8n8.x4.shared.b16 {%0,%1,%2,%3},[%4];"
                    : "=r"(b[nj4 * 2][0]), "=r"(b[nj4 * 2][1]),
                      "=r"(b[nj4 * 2 + 1][0]), "=r"(b[nj4 * 2 + 1][1])
                    : "r"(addr));
            }
#pragma unroll
            for (int mi = 0; mi < 4; mi++)
#pragma unroll
                for (int nj = 0; nj < 8; nj++)
                    asm volatile(
                        "mma.sync.aligned.m16n8k16.row.col.f32.bf16.bf16.f32 "
                        "{%0,%1,%2,%3},{%4,%5,%6,%7},{%8,%9},{%0,%1,%2,%3};"
                        : "+f"(acc[mi][nj][0]), "+f"(acc[mi][nj][1]),
                          "+f"(acc[mi][nj][2]), "+f"(acc[mi][nj][3])
                        : "r"(a[mi][0]), "r"(a[mi][1]), "r"(a[mi][2]), "r"(a[mi][3]),
                          "r"(b[nj][0]), "r"(b[nj][1]));
        }
        __syncthreads();
    }

    // epilogue
    const int g = lane >> 2;
    const int c = lane & 3;
#pragma unroll
    for (int mi = 0; mi < 4; mi++) {
#pragma unroll
        for (int nj = 0; nj < 8; nj++) {
            int row0 = by * 128 + wm + mi * 16 + g;
            int row1 = row0 + 8;
            int col  = bx * 128 + wn + nj * 8 + c * 2;
            float v0 = acc[mi][nj][0], v1 = acc[mi][nj][1];
            float v2 = acc[mi][nj][2], v3 = acc[mi][nj][3];
            if (MASKED) {
                unsigned w0 = maskbits[(size_t)row0 * (N / 32) + (col >> 5)];
                unsigned w1 = maskbits[(size_t)row1 * (N / 32) + (col >> 5)];
                if (!((w0 >> (col & 31)) & 1u))       v0 = -FLT_MAX;
                if (!((w0 >> ((col + 1) & 31)) & 1u)) v1 = -FLT_MAX;
                if (!((w1 >> (col & 31)) & 1u))       v2 = -FLT_MAX;
                if (!((w1 >> ((col + 1) & 31)) & 1u)) v3 = -FLT_MAX;
            }
            *reinterpret_cast<float2*>(&Csel[(size_t)row0 * N + col]) = make_float2(v0, v1);
            *reinterpret_cast<float2*>(&Csel[(size_t)row1 * N + col]) = make_float2(v2, v3);
        }
    }
}

// ============================================================
// fp32 -> split bf16 packing. mode 0: [hi|hi|lo], mode 1: [hi|lo|hi]
// ============================================================
__global__ void pack_split_kernel(const float* __restrict__ in,
                                  __nv_bfloat16* __restrict__ out,
                                  int R, int C, int mode)
{
    int total = R * C;
    for (int idx = blockIdx.x * blockDim.x + threadIdx.x; idx < total;
         idx += gridDim.x * blockDim.x) {
        int r = idx / C, c = idx - r * C;
        float v = in[idx];
        __nv_bfloat16 hi = __float2bfloat16(v);
        __nv_bfloat16 lo = __float2bfloat16(v - __bfloat162float(hi));
        size_t base = (size_t)r * 3 * C;
        out[base + c]         = hi;
        out[base + C + c]     = mode ? lo : hi;
        out[base + 2 * C + c] = mode ? hi : lo;
    }
}

// Transpose + B-pattern pack: in[R x C] fp32 -> out[C x 3R] bf16 (hi|lo|hi)
__global__ void transpose_pack_kernel(const float* __restrict__ in,
                                      __nv_bfloat16* __restrict__ out,
                                      int R, int C)
{
    __shared__ float t[32][33];
    int rb = blockIdx.y * 32;
    int cb = blockIdx.x * 32;
    int tx = threadIdx.x;
    int ty0 = threadIdx.y;
#pragma unroll
    for (int p = 0; p < 4; p++) {
        int ty = ty0 + p * 8;
        t[ty][tx] = in[(size_t)(rb + ty) * C + cb + tx];
    }
    __syncthreads();
#pragma unroll
    for (int p = 0; p < 4; p++) {
        int ty = ty0 + p * 8;
        float v = t[tx][ty];
        __nv_bfloat16 hi = __float2bfloat16(v);
        __nv_bfloat16 lo = __float2bfloat16(v - __bfloat162float(hi));
        size_t base = (size_t)(cb + ty) * 3 * R;
        out[base + rb + tx]         = hi;
        out[base + R + rb + tx]     = lo;
        out[base + 2 * R + rb + tx] = hi;
    }
}

// ============================================================
__global__ void src_dst_kernel(const float* __restrict__ Wh, const float* __restrict__ r,
                               float* __restrict__ src, float* __restrict__ dst)
{
    int warp = (blockIdx.x * blockDim.x + threadIdx.x) >> 5;
    int lane = threadIdx.x & 31;
    if (warp >= NN) return;
    const float* row = Wh + (size_t)warp * FF;
    float a = 0.f, b = 0.f;
    for (int f = lane; f < FF; f += 32) {
        float v = row[f];
        a = fmaf(v, r[f], a);
        b = fmaf(v, r[FF + f], b);
    }
#pragma unroll
    for (int s = 16; s > 0; s >>= 1) {
        a += __shfl_xor_sync(0xffffffffu, a, s);
        b += __shfl_xor_sync(0xffffffffu, b, s);
    }
    if (lane == 0) { src[warp] = a; dst[warp] = b; }
}

// ============================================================
// Short-distance attention (sparse), fused softmax + SpMM + gelu.
// Also emits the bit-packed adjacency row (fused, saves a 64MB re-read).
// ============================================================
__global__ void __launch_bounds__(256) short_attn_kernel(
    const float* __restrict__ A, const float* __restrict__ Wh,
    const float* __restrict__ src, const float* __restrict__ dst,
    float* __restrict__ hk, unsigned* __restrict__ bits)
{
    __shared__ int      s_idx[NN];
    __shared__ float    s_w[NN];
    __shared__ int      s_scan[256];
    __shared__ float    s_red[256];
    __shared__ unsigned s_m16[256];

    const int i   = blockIdx.x;
    const int tid = threadIdx.x;
    const float* Arow = A + (size_t)i * NN;

    const int base = tid * 16;
    unsigned m16 = 0; int c = 0;
#pragma unroll
    for (int q = 0; q < 16; q++)
        if (Arow[base + q] != 0.0f) { m16 |= (1u << q); c++; }
    s_m16[tid] = m16;
    s_scan[tid] = c;
    __syncthreads();
    // fused adjacency bitset output (one 32-bit word per 2 threads)
    if (tid < WRDS)
        bits[(size_t)i * WRDS + tid] = s_m16[2 * tid] | (s_m16[2 * tid + 1] << 16);
#pragma unroll
    for (int s = 1; s < 256; s <<= 1) {
        int v = (tid >= s) ? s_scan[tid - s] : 0;
        __syncthreads();
        s_scan[tid] += v;
        __syncthreads();
    }
    int start = s_scan[tid] - c;
    int cnt   = s_scan[255];
    {
        int p = start;
#pragma unroll
        for (int q = 0; q < 16; q++)
            if ((m16 >> q) & 1u) s_idx[p++] = base + q;
    }
    __syncthreads();

    float si = src[i];
    float lmax = -FLT_MAX;
    for (int p = tid; p < cnt; p += 256) {
        float e = si + dst[s_idx[p]];
        e = (e > 0.f) ? e : 0.2f * e;
        s_w[p] = e;
        lmax = fmaxf(lmax, e);
    }
    s_red[tid] = lmax;
    __syncthreads();
#pragma unroll
    for (int s = 128; s > 0; s >>= 1) {
        if (tid < s) s_red[tid] = fmaxf(s_red[tid], s_red[tid + s]);
        __syncthreads();
    }
    float mx = s_red[0];
    __syncthreads();

    float lsum = 0.f;
    for (int p = tid; p < cnt; p += 256) {
        float w = expf(s_w[p] - mx);
        s_w[p] = w;
        lsum += w;
    }
    s_red[tid] = lsum;
    __syncthreads();
#pragma unroll
    for (int s = 128; s > 0; s >>= 1) {
        if (tid < s) s_red[tid] += s_red[tid + s];
        __syncthreads();
    }
    float inv = 1.0f / s_red[0];
    __syncthreads();

    float a0 = 0.f, a1 = 0.f;
    for (int p = 0; p < cnt; p++) {
        float w = s_w[p];
        const float* whr = Wh + (size_t)s_idx[p] * FF;
        a0 = fmaf(w, whr[tid],       a0);
        a1 = fmaf(w, whr[tid + 256], a1);
    }
    hk[(size_t)i * FF + tid]       = gelu_tanh(a0 * inv);
    hk[(size_t)i * FF + tid + 256] = gelu_tanh(a1 * inv);
}

// ============================================================
__global__ void hop_step_kernel(const unsigned* __restrict__ Abits,
                                const unsigned* __restrict__ src,
                                unsigned* __restrict__ dst,
                                int iter, const int* __restrict__ num_hops)
{
    __shared__ unsigned s_row[WRDS];
    const int i = blockIdx.x;
    const int t = threadIdx.x;
    s_row[t] = Abits[i * WRDS + t];
    __syncthreads();

    if (iter >= (*num_hops) - 1) {
        dst[i * WRDS + t] = src[i * WRDS + t];
        return;
    }
    unsigned acc = 0;
    for (int w = 0; w < WRDS; w++) {
        unsigned bits = s_row[w];
        while (bits) {
            int b = __ffs(bits) - 1;
            bits &= bits - 1;
            acc |= src[(size_t)(w * 32 + b) * WRDS + t];
        }
    }
    dst[i * WRDS + t] = acc;
}

// ============================================================
// Row softmax (4096-wide) fused with [hi|lo] bf16 packing (stride 8192)
// ============================================================
__global__ void __launch_bounds__(256) softmax_pack_kernel(
    const float* __restrict__ S, __nv_bfloat16* __restrict__ attP)
{
    __shared__ float s_red[256];
    const int i   = blockIdx.x;
    const int tid = threadIdx.x;
    const float* row = S + (size_t)i * NN;
    __nv_bfloat16* orow = attP + (size_t)i * KATT;

    float vals[16];
    float lmax = -FLT_MAX;
#pragma unroll
    for (int p = 0; p < 16; p++) {
        vals[p] = row[tid + p * 256];
        lmax = fmaxf(lmax, vals[p]);
    }
    s_red[tid] = lmax;
    __syncthreads();
#pragma unroll
    for (int s = 128; s > 0; s >>= 1) {
        if (tid < s) s_red[tid] = fmaxf(s_red[tid], s_red[tid + s]);
        __syncthreads();
    }
    float mx = s_red[0];
    __syncthreads();

    float lsum = 0.f;
#pragma unroll
    for (int p = 0; p < 16; p++) {
        float w = expf(vals[p] - mx);
        vals[p] = w;
        lsum += w;
    }
    s_red[tid] = lsum;
    __syncthreads();
#pragma unroll
    for (int s = 128; s > 0; s >>= 1) {
        if (tid < s) s_red[tid] += s_red[tid + s];
        __syncthreads();
    }
    float inv = 1.0f / s_red[0];
#pragma unroll
    for (int p = 0; p < 16; p++) {
        int j = tid + p * 256;
        float a = vals[p] * inv;
        __nv_bfloat16 hi = __float2bfloat16(a);
        __nv_bfloat16 lo = __float2bfloat16(a - __bfloat162float(hi));
        orow[j]      = hi;
        orow[NN + j] = lo;
    }
}

// ============================================================
// out = sum of NSPLIT partials  (4096 x 512 fp32)
// ============================================================
__global__ void reduceN_kernel(const float* __restrict__ part, float* __restrict__ out)
{
    int total = NN * FF / 4;
    const size_t stride = (size_t)NN * FF / 4;
    for (int idx = blockIdx.x * blockDim.x + threadIdx.x; idx < total;
         idx += gridDim.x * blockDim.x) {
        float4 o = make_float4(0.f, 0.f, 0.f, 0.f);
#pragma unroll
        for (int s = 0; s < NSPLIT; s++) {
            float4 a = reinterpret_cast<const float4*>(part)[idx + s * stride];
            o.x += a.x; o.y += a.y; o.z += a.z; o.w += a.w;
        }
        reinterpret_cast<float4*>(out)[idx] = o;
    }
}

// ============================================================
// Host launch
// ============================================================
extern "C" void kernel_launch(void* const* d_in, const int* in_sizes, int n_in,
                              void* d_out, int out_size)
{
    const float* X  = (const float*)d_in[0];
    const float* A  = (const float*)d_in[1];
    const float* Ws = (const float*)d_in[2];
    const float* r  = (const float*)d_in[3];
    const float* Wl = (const float*)d_in[4];
    const int*   nh = (const int*)d_in[5];
    float* out = (float*)d_out;

    float *Wh, *Wa, *hk, *src, *dst, *S, *part;
    unsigned *Abits, *P, *Q;
    __nv_bfloat16 *Xp, *WsP, *WlP, *hkP, *WaP, *hkTP, *attP;
    cudaGetSymbolAddress((void**)&Wh,    g_Wh);
    cudaGetSymbolAddress((void**)&Wa,    g_Wa);
    cudaGetSymbolAddress((void**)&hk,    g_hk);
    cudaGetSymbolAddress((void**)&src,   g_src);
    cudaGetSymbolAddress((void**)&dst,   g_dst);
    cudaGetSymbolAddress((void**)&S,     g_S);
    cudaGetSymbolAddress((void**)&Abits, g_Abits);
    cudaGetSymbolAddress((void**)&P,     g_P);
    cudaGetSymbolAddress((void**)&Q,     g_Q);
    cudaGetSymbolAddress((void**)&Xp,    g_Xp);
    cudaGetSymbolAddress((void**)&WsP,   g_WsP);
    cudaGetSymbolAddress((void**)&WlP,   g_WlP);
    cudaGetSymbolAddress((void**)&hkP,   g_hkP);
    cudaGetSymbolAddress((void**)&WaP,   g_WaP);
    cudaGetSymbolAddress((void**)&hkTP,  g_hkTP);
    cudaGetSymbolAddress((void**)&attP,  g_attP);
    cudaGetSymbolAddress((void**)&part,  g_part);

    const int smemBytes = NSTG * 2 * 128 * SSTR * 2;   // 73728
    cudaFuncSetAttribute(mma_gemm_nt<false, false, true, false>,
                         cudaFuncAttributeMaxDynamicSharedMemorySize, smemBytes);
    cudaFuncSetAttribute(mma_gemm_nt<true, false, false, false>,
                         cudaFuncAttributeMaxDynamicSharedMemorySize, smemBytes);
    cudaFuncSetAttribute(mma_gemm_nt<false, true, false, true>,
                         cudaFuncAttributeMaxDynamicSharedMemorySize, smemBytes);

    // pack inputs to split-bf16
    pack_split_kernel<<<1024, 256>>>(X,  Xp,  NN, FF, 0);
    pack_split_kernel<<<256,  256>>>(Ws, WsP, FF, FF, 1);
    pack_split_kernel<<<256,  256>>>(Wl, WlP, FF, FF, 1);

    // Wh = X Ws^T and Wa = X Wl^T in ONE dual launch
    mma_gemm_nt<false, false, true, false><<<dim3(FF / 128, NN / 128, 2), 128, smemBytes>>>(
        Xp, WsP, WlP, Wh, Wa, NN, FF, K3S, K3S, K3S, nullptr);

    // src/dst + short attention (emits Abits too) -> hk
    src_dst_kernel<<<NN / 8, 256>>>(Wh, r, src, dst);
    short_attn_kernel<<<NN, 256>>>(A, Wh, src, dst, hk, Abits);

    // pack hk (A-pattern), Wa (B-pattern), hk^T (B-pattern)
    pack_split_kernel<<<1024, 256>>>(hk, hkP, NN, FF, 0);
    pack_split_kernel<<<1024, 256>>>(Wa, WaP, NN, FF, 1);
    transpose_pack_kernel<<<dim3(FF / 32, NN / 32), dim3(32, 8)>>>(hk, hkTP, NN, FF);

    // multi-hop reachability (boolean), guarded launches; result in Q
    hop_step_kernel<<<NN, WRDS>>>(Abits, Abits, P, 0, nh);
    hop_step_kernel<<<NN, WRDS>>>(Abits, P, Q, 1, nh);
    hop_step_kernel<<<NN, WRDS>>>(Abits, Q, P, 2, nh);
    hop_step_kernel<<<NN, WRDS>>>(Abits, P, Q, 3, nh);
    hop_step_kernel<<<NN, WRDS>>>(Abits, Q, P, 4, nh);
    hop_step_kernel<<<NN, WRDS>>>(Abits, P, Q, 5, nh);

    // scores = hk Wa^T with reach mask -> S (fp32)
    mma_gemm_nt<true, false, false, false><<<dim3(NN / 128, NN / 128), 128, smemBytes>>>(
        hkP, WaP, nullptr, S, nullptr, NN, NN, K3S, K3S, K3S, Q);

    // softmax + pack att to [hi|lo] bf16 (stride 8192)
    softmax_pack_kernel<<<NN, 256>>>(S, attP);

    // ok = att2 hk  (split-K = 6 -> grid 768 ≈ 2 clean waves at occ 3) + reduce
    mma_gemm_nt<false, true, false, true><<<dim3(FF / 128, NN / 128, NSPLIT), 128, smemBytes>>>(
        attP, hkTP, nullptr, part, nullptr, NN, FF, K3N, K3N / NSPLIT, KATT, nullptr);
    reduceN_kernel<<<1024, 256>>>(part, out);
}

// round 12
// speedup vs baseline: 1.0907x; 1.0145x over previous
#include <cuda_runtime.h>
#include <cuda_bf16.h>
#include <float.h>
#include <stdint.h>

// Problem dims (fixed by setup_inputs)
#define NN   4096
#define FF   512
#define WRDS (NN / 32)
#define K3S  (3 * FF)      // 1536  packed K for feature-dim GEMMs
#define K3N  (3 * NN)      // 12288 logical K for the att@hk GEMM
#define KATT 8192          // physical att row stride: [hi(4096) | lo(4096)]
#define NSPLIT 8

// ---------------- device scratch (no allocations allowed) ----------------
__device__ float         g_Wh[NN * FF];
__device__ float         g_Wa[NN * FF];
__device__ float         g_hk[NN * FF];
__device__ float         g_src[NN];
__device__ float         g_dst[NN];
__device__ unsigned      g_Abits[NN * WRDS];
__device__ unsigned      g_P[NN * WRDS];
__device__ unsigned      g_Q[NN * WRDS];
__device__ float         g_S[(size_t)NN * NN];          // 64 MB scores
__device__ __nv_bfloat16 g_Xp [(size_t)NN * K3S];
__device__ __nv_bfloat16 g_WsP[(size_t)FF * K3S];
__device__ __nv_bfloat16 g_WlP[(size_t)FF * K3S];
__device__ __nv_bfloat16 g_hkP[(size_t)NN * K3S];
__device__ __nv_bfloat16 g_WaP[(size_t)NN * K3S];
__device__ __nv_bfloat16 g_hkTP[(size_t)FF * K3N];
__device__ __nv_bfloat16 g_attP[(size_t)NN * KATT];     // 64 MB [hi|lo]
__device__ float         g_part[NSPLIT][(size_t)NN * FF]; // 64 MB split-K partials

// ---------------- helpers ----------------
__device__ __forceinline__ float gelu_tanh(float x) {
    float x3 = x * x * x;
    return 0.5f * x * (1.0f + tanhf(0.7978845608028654f * (x + 0.044715f * x3)));
}
__device__ __forceinline__ uint32_t smem_u32(const void* p) {
    return (uint32_t)__cvta_generic_to_shared(p);
}

// ============================================================
// Tensor-core bf16 NT GEMM: C[M,N] = A[M,Kslice] * B[N,Kslice]^T
// CTA 128x128, 4 warps (2x2), warp tile 64x64, BK=64, 2-stage cp.async.
// DUAL:   z selects B vs B2 (low bit when combined with SPLITK)
// SPLITK: z selects K slice; partials C += slab*M*N   (slab = bz)
// MASKED: reach-mask epilogue (masked -> -FLT_MAX)
// REMAP:  A-side logical k>=4096 reads physical k-4096 (hi-plane reuse)
// strideA: physical A row stride (== K unless REMAP)
// ============================================================
#define BK     64
#define SSTR   72            // padded halfs per row (144B, 16B multiple)
#define NSTG   2

template <bool MASKED, bool SPLITK, bool DUAL, bool REMAP>
__global__ void __launch_bounds__(128, 3) mma_gemm_nt(
    const __nv_bfloat16* __restrict__ A,
    const __nv_bfloat16* __restrict__ B,
    const __nv_bfloat16* __restrict__ B2,
    float* __restrict__ C,
    float* __restrict__ C2,
    int M, int N, int K, int kSlice, int strideA,
    const unsigned* __restrict__ maskbits)
{
    extern __shared__ __align__(16) unsigned char smem_raw[];
    __nv_bfloat16* AsBase = (__nv_bfloat16*)smem_raw;                 // [NSTG][128][SSTR]
    __nv_bfloat16* BsBase = AsBase + NSTG * 128 * SSTR;

    const int tid  = threadIdx.x;
    const int bx   = blockIdx.x;    // N tile
    const int by   = blockIdx.y;    // M tile
    const int bz   = blockIdx.z;
    const int warp = tid >> 5;
    const int lane = tid & 31;
    const int wm   = (warp >> 1) * 64;
    const int wn   = (warp & 1) * 64;

    const int dsel = DUAL ? (bz & 1) : 0;
    const int kz   = SPLITK ? (DUAL ? (bz >> 1) : bz) : 0;

    const __nv_bfloat16* Bsel = dsel ? B2 : B;
    int kBegin = SPLITK ? kz * kSlice : 0;
    int kLen   = SPLITK ? kSlice : K;
    float* Csel;
    if (SPLITK)      Csel = C + (size_t)bz * M * N;          // slab per z
    else if (DUAL)   Csel = dsel ? C2 : C;
    else             Csel = C;

    const __nv_bfloat16* Arow = A    + (size_t)(by * 128) * strideA;
    const __nv_bfloat16* Bg   = Bsel + (size_t)(bx * 128) * K + kBegin;

    float acc[4][8][4];
#pragma unroll
    for (int mi = 0; mi < 4; mi++)
#pragma unroll
        for (int nj = 0; nj < 8; nj++)
#pragma unroll
            for (int q = 0; q < 4; q++) acc[mi][nj][q] = 0.0f;

    const int nK = kLen / BK;   // BK=64 chunks

    auto load_stage = [&](int s, int kc) {
        __nv_bfloat16* As = AsBase + s * 128 * SSTR;
        __nv_bfloat16* Bs = BsBase + s * 128 * SSTR;
        int colL = kBegin + kc * BK;                    // logical A column
        int colP = REMAP ? (colL < NN ? colL : colL - NN) : colL;
#pragma unroll
        for (int j = 0; j < 8; j++) {
            int idx = tid + j * 128;        // 1024 chunks of 16B per matrix
            int row = idx >> 3;             // 0..127
            int c   = idx & 7;              // 16B chunk within 128B row
            uint32_t sa = smem_u32(&As[row * SSTR + c * 8]);
            const void* ga = Arow + (size_t)row * strideA + colP + c * 8;
            asm volatile("cp.async.cg.shared.global [%0], [%1], 16;" :: "r"(sa), "l"(ga));
            uint32_t sb = smem_u32(&Bs[row * SSTR + c * 8]);
            const void* gb = Bg + (size_t)row * K + kc * BK + c * 8;
            asm volatile("cp.async.cg.shared.global [%0], [%1], 16;" :: "r"(sb), "l"(gb));
        }
    };

    load_stage(0, 0);
    asm volatile("cp.async.commit_group;");

    for (int kc = 0; kc < nK; kc++) {
        const int s = kc & 1;
        if (kc + 1 < nK) {
            load_stage(s ^ 1, kc + 1);
            asm volatile("cp.async.commit_group;");
            asm volatile("cp.async.wait_group 1;");
        } else {
            asm volatile("cp.async.wait_group 0;");
        }
        __syncthreads();

        const __nv_bfloat16* As = AsBase + s * 128 * SSTR;
        const __nv_bfloat16* Bs = BsBase + s * 128 * SSTR;

#pragma unroll
        for (int kk = 0; kk < BK; kk += 16) {
            uint32_t a[4][4];
#pragma unroll
            for (int mi = 0; mi < 4; mi++) {
                int row = wm + mi * 16 + (lane & 7) + ((lane >> 3) & 1) * 8;
                int col = kk + (lane >> 4) * 8;
                uint32_t addr = smem_u32(&As[row * SSTR + col]);
                asm volatile("ldmatrix.sync.aligned.m8n8.x4.shared.b16 {%0,%1,%2,%3},[%4];"
                    : "=r"(a[mi][0]), "=r"(a[mi][1]), "=r"(a[mi][2]), "=r"(a[mi][3])
                    : "r"(addr));
            }
            uint32_t b[8][2];
#pragma unroll
            for (int nj4 = 0; nj4 < 4; nj4++) {
                int row = wn + nj4 * 16 + (lane & 7) + (lane >> 4) * 8;
                int col = kk + ((lane >> 3) & 1) * 8;
                uint32_t addr = smem_u32(&Bs[row * SSTR + col]);
                asm volatile("ldmatrix.sync.aligned.m8n8.x4.shared.b16 {%0,%1,%2,%3},[%4];"
                    : "=r"(b[nj4 * 2][0]), "=r"(b[nj4 * 2][1]),
                      "=r"(b[nj4 * 2 + 1][0]), "=r"(b[nj4 * 2 + 1][1])
                    : "r"(addr));
            }
#pragma unroll
            for (int mi = 0; mi < 4; mi++)
#pragma unroll
                for (int nj = 0; nj < 8; nj++)
                    asm volatile(
                        "mma.sync.aligned.m16n8k16.row.col.f32.bf16.bf16.f32 "
                        "{%0,%1,%2,%3},{%4,%5,%6,%7},{%8,%9},{%0,%1,%2,%3};"
                        : "+f"(acc[mi][nj][0]), "+f"(acc[mi][nj][1]),
                          "+f"(acc[mi][nj][2]), "+f"(acc[mi][nj][3])
                        : "r"(a[mi][0]), "r"(a[mi][1]), "r"(a[mi][2]), "r"(a[mi][3]),
                          "r"(b[nj][0]), "r"(b[nj][1]));
        }
        __syncthreads();
    }

    // epilogue
    const int g = lane >> 2;
    const int c = lane & 3;
#pragma unroll
    for (int mi = 0; mi < 4; mi++) {
#pragma unroll
        for (int nj = 0; nj < 8; nj++) {
            int row0 = by * 128 + wm + mi * 16 + g;
            int row1 = row0 + 8;
            int col  = bx * 128 + wn + nj * 8 + c * 2;
            float v0 = acc[mi][nj][0], v1 = acc[mi][nj][1];
            float v2 = acc[mi][nj][2], v3 = acc[mi][nj][3];
            if (MASKED) {
                unsigned w0 = maskbits[(size_t)row0 * (N / 32) + (col >> 5)];
                unsigned w1 = maskbits[(size_t)row1 * (N / 32) + (col >> 5)];
                if (!((w0 >> (col & 31)) & 1u))       v0 = -FLT_MAX;
                if (!((w0 >> ((col + 1) & 31)) & 1u)) v1 = -FLT_MAX;
                if (!((w1 >> (col & 31)) & 1u))       v2 = -FLT_MAX;
                if (!((w1 >> ((col + 1) & 31)) & 1u)) v3 = -FLT_MAX;
            }
            *reinterpret_cast<float2*>(&Csel[(size_t)row0 * N + col]) = make_float2(v0, v1);
            *reinterpret_cast<float2*>(&Csel[(size_t)row1 * N + col]) = make_float2(v2, v3);
        }
    }
}

// ============================================================
// fp32 -> split bf16 packing. mode 0: [hi|hi|lo], mode 1: [hi|lo|hi]
// ============================================================
__global__ void pack_split_kernel(const float* __restrict__ in,
                                  __nv_bfloat16* __restrict__ out,
                                  int R, int C, int mode)
{
    int total = R * C;
    for (int idx = blockIdx.x * blockDim.x + threadIdx.x; idx < total;
         idx += gridDim.x * blockDim.x) {
        int r = idx / C, c = idx - r * C;
        float v = in[idx];
        __nv_bfloat16 hi = __float2bfloat16(v);
        __nv_bfloat16 lo = __float2bfloat16(v - __bfloat162float(hi));
        size_t base = (size_t)r * 3 * C;
        out[base + c]         = hi;
        out[base + C + c]     = mode ? lo : hi;
        out[base + 2 * C + c] = mode ? hi : lo;
    }
}

// Transpose + B-pattern pack: in[R x C] fp32 -> out[C x 3R] bf16 (hi|lo|hi)
__global__ void transpose_pack_kernel(const float* __restrict__ in,
                                      __nv_bfloat16* __restrict__ out,
                                      int R, int C)
{
    __shared__ float t[32][33];
    int rb = blockIdx.y * 32;
    int cb = blockIdx.x * 32;
    int tx = threadIdx.x;
    int ty0 = threadIdx.y;
#pragma unroll
    for (int p = 0; p < 4; p++) {
        int ty = ty0 + p * 8;
        t[ty][tx] = in[(size_t)(rb + ty) * C + cb + tx];
    }
    __syncthreads();
#pragma unroll
    for (int p = 0; p < 4; p++) {
        int ty = ty0 + p * 8;
        float v = t[tx][ty];
        __nv_bfloat16 hi = __float2bfloat16(v);
        __nv_bfloat16 lo = __float2bfloat16(v - __bfloat162float(hi));
        size_t base = (size_t)(cb + ty) * 3 * R;
        out[base + rb + tx]         = hi;
        out[base + R + rb + tx]     = lo;
        out[base + 2 * R + rb + tx] = hi;
    }
}

// ============================================================
// Wh = p0 + p2 ; Wa = p1 + p3   (dual split-K reduce, 4096x512 each)
// ============================================================
__global__ void reduce_dual_kernel(const float* __restrict__ part,
                                   float* __restrict__ Wh, float* __restrict__ Wa)
{
    int total = NN * FF / 4;
    const size_t stride = (size_t)NN * FF / 4;
    for (int idx = blockIdx.x * blockDim.x + threadIdx.x; idx < total;
         idx += gridDim.x * blockDim.x) {
        float4 a0 = reinterpret_cast<const float4*>(part)[idx];
        float4 a2 = reinterpret_cast<const float4*>(part)[idx + 2 * stride];
        float4 a1 = reinterpret_cast<const float4*>(part)[idx + stride];
        float4 a3 = reinterpret_cast<const float4*>(part)[idx + 3 * stride];
        float4 h, w;
        h.x = a0.x + a2.x; h.y = a0.y + a2.y; h.z = a0.z + a2.z; h.w = a0.w + a2.w;
        w.x = a1.x + a3.x; w.y = a1.y + a3.y; w.z = a1.z + a3.z; w.w = a1.w + a3.w;
        reinterpret_cast<float4*>(Wh)[idx] = h;
        reinterpret_cast<float4*>(Wa)[idx] = w;
    }
}

// ============================================================
__global__ void src_dst_kernel(const float* __restrict__ Wh, const float* __restrict__ r,
                               float* __restrict__ src, float* __restrict__ dst)
{
    int warp = (blockIdx.x * blockDim.x + threadIdx.x) >> 5;
    int lane = threadIdx.x & 31;
    if (warp >= NN) return;
    const float* row = Wh + (size_t)warp * FF;
    float a = 0.f, b = 0.f;
    for (int f = lane; f < FF; f += 32) {
        float v = row[f];
        a = fmaf(v, r[f], a);
        b = fmaf(v, r[FF + f], b);
    }
#pragma unroll
    for (int s = 16; s > 0; s >>= 1) {
        a += __shfl_xor_sync(0xffffffffu, a, s);
        b += __shfl_xor_sync(0xffffffffu, b, s);
    }
    if (lane == 0) { src[warp] = a; dst[warp] = b; }
}

// ============================================================
// Short-distance attention (sparse), fused softmax + SpMM + gelu.
// Also emits the bit-packed adjacency row (fused, saves a 64MB re-read).
// ============================================================
__global__ void __launch_bounds__(256) short_attn_kernel(
    const float* __restrict__ A, const float* __restrict__ Wh,
    const float* __restrict__ src, const float* __restrict__ dst,
    float* __restrict__ hk, unsigned* __restrict__ bits)
{
    __shared__ int      s_idx[NN];
    __shared__ float    s_w[NN];
    __shared__ int      s_scan[256];
    __shared__ float    s_red[256];
    __shared__ unsigned s_m16[256];

    const int i   = blockIdx.x;
    const int tid = threadIdx.x;
    const float* Arow = A + (size_t)i * NN;

    const int base = tid * 16;
    unsigned m16 = 0; int c = 0;
#pragma unroll
    for (int q = 0; q < 16; q++)
        if (Arow[base + q] != 0.0f) { m16 |= (1u << q); c++; }
    s_m16[tid] = m16;
    s_scan[tid] = c;
    __syncthreads();
    // fused adjacency bitset output (one 32-bit word per 2 threads)
    if (tid < WRDS)
        bits[(size_t)i * WRDS + tid] = s_m16[2 * tid] | (s_m16[2 * tid + 1] << 16);
#pragma unroll
    for (int s = 1; s < 256; s <<= 1) {
        int v = (tid >= s) ? s_scan[tid - s] : 0;
        __syncthreads();
        s_scan[tid] += v;
        __syncthreads();
    }
    int start = s_scan[tid] - c;
    int cnt   = s_scan[255];
    {
        int p = start;
#pragma unroll
        for (int q = 0; q < 16; q++)
            if ((m16 >> q) & 1u) s_idx[p++] = base + q;
    }
    __syncthreads();

    float si = src[i];
    float lmax = -FLT_MAX;
    for (int p = tid; p < cnt; p += 256) {
        float e = si + dst[s_idx[p]];
        e = (e > 0.f) ? e : 0.2f * e;
        s_w[p] = e;
        lmax = fmaxf(lmax, e);
    }
    s_red[tid] = lmax;
    __syncthreads();
#pragma unroll
    for (int s = 128; s > 0; s >>= 1) {
        if (tid < s) s_red[tid] = fmaxf(s_red[tid], s_red[tid + s]);
        __syncthreads();
    }
    float mx = s_red[0];
    __syncthreads();

    float lsum = 0.f;
    for (int p = tid; p < cnt; p += 256) {
        float w = expf(s_w[p] - mx);
        s_w[p] = w;
        lsum += w;
    }
    s_red[tid] = lsum;
    __syncthreads();
#pragma unroll
    for (int s = 128; s > 0; s >>= 1) {
        if (tid < s) s_red[tid] += s_red[tid + s];
        __syncthreads();
    }
    float inv = 1.0f / s_red[0];
    __syncthreads();

    float a0 = 0.f, a1 = 0.f;
    for (int p = 0; p < cnt; p++) {
        float w = s_w[p];
        const float* whr = Wh + (size_t)s_idx[p] * FF;
        a0 = fmaf(w, whr[tid],       a0);
        a1 = fmaf(w, whr[tid + 256], a1);
    }
    hk[(size_t)i * FF + tid]       = gelu_tanh(a0 * inv);
    hk[(size_t)i * FF + tid + 256] = gelu_tanh(a1 * inv);
}

// ============================================================
__global__ void hop_step_kernel(const unsigned* __restrict__ Abits,
                                const unsigned* __restrict__ src,
                                unsigned* __restrict__ dst,
                                int iter, const int* __restrict__ num_hops)
{
    __shared__ unsigned s_row[WRDS];
    const int i = blockIdx.x;
    const int t = threadIdx.x;
    s_row[t] = Abits[i * WRDS + t];
    __syncthreads();

    if (iter >= (*num_hops) - 1) {
        dst[i * WRDS + t] = src[i * WRDS + t];
        return;
    }
    unsigned acc = 0;
    for (int w = 0; w < WRDS; w++) {
        unsigned bits = s_row[w];
        while (bits) {
            int b = __ffs(bits) - 1;
            bits &= bits - 1;
            acc |= src[(size_t)(w * 32 + b) * WRDS + t];
        }
    }
    dst[i * WRDS + t] = acc;
}

// ============================================================
// Row softmax (4096-wide) fused with [hi|lo] bf16 packing (stride 8192)
// ============================================================
__global__ void __launch_bounds__(256) softmax_pack_kernel(
    const float* __restrict__ S, __nv_bfloat16* __restrict__ attP)
{
    __shared__ float s_red[256];
    const int i   = blockIdx.x;
    const int tid = threadIdx.x;
    const float* row = S + (size_t)i * NN;
    __nv_bfloat16* orow = attP + (size_t)i * KATT;

    float vals[16];
    float lmax = -FLT_MAX;
#pragma unroll
    for (int p = 0; p < 16; p++) {
        vals[p] = row[tid + p * 256];
        lmax = fmaxf(lmax, vals[p]);
    }
    s_red[tid] = lmax;
    __syncthreads();
#pragma unroll
    for (int s = 128; s > 0; s >>= 1) {
        if (tid < s) s_red[tid] = fmaxf(s_red[tid], s_red[tid + s]);
        __syncthreads();
    }
    float mx = s_red[0];
    __syncthreads();

    float lsum = 0.f;
#pragma unroll
    for (int p = 0; p < 16; p++) {
        float w = expf(vals[p] - mx);
        vals[p] = w;
        lsum += w;
    }
    s_red[tid] = lsum;
    __syncthreads();
#pragma unroll
    for (int s = 128; s > 0; s >>= 1) {
        if (tid < s) s_red[tid] += s_red[tid + s];
        __syncthreads();
    }
    float inv = 1.0f / s_red[0];
#pragma unroll
    for (int p = 0; p < 16; p++) {
        int j = tid + p * 256;
        float a = vals[p] * inv;
        __nv_bfloat16 hi = __float2bfloat16(a);
        __nv_bfloat16 lo = __float2bfloat16(a - __bfloat162float(hi));
        orow[j]      = hi;
        orow[NN + j] = lo;
    }
}

// ============================================================
// out = sum of NSPLIT partials  (4096 x 512 fp32)
// ============================================================
__global__ void reduceN_kernel(const float* __restrict__ part, float* __restrict__ out)
{
    int total = NN * FF / 4;
    const size_t stride = (size_t)NN * FF / 4;
    for (int idx = blockIdx.x * blockDim.x + threadIdx.x; idx < total;
         idx += gridDim.x * blockDim.x) {
        float4 o = make_float4(0.f, 0.f, 0.f, 0.f);
#pragma unroll
        for (int s = 0; s < NSPLIT; s++) {
            float4 a = reinterpret_cast<const float4*>(part)[idx + s * stride];
            o.x += a.x; o.y += a.y; o.z += a.z; o.w += a.w;
        }
        reinterpret_cast<float4*>(out)[idx] = o;
    }
}

// ============================================================
// Host launch
// ============================================================
extern "C" void kernel_launch(void* const* d_in, const int* in_sizes, int n_in,
                              void* d_out, int out_size)
{
    const float* X  = (const float*)d_in[0];
    const float* A  = (const float*)d_in[1];
    const float* Ws = (const float*)d_in[2];
    const float* r  = (const float*)d_in[3];
    const float* Wl = (const float*)d_in[4];
    const int*   nh = (const int*)d_in[5];
    float* out = (float*)d_out;

    float *Wh, *Wa, *hk, *src, *dst, *S, *part;
    unsigned *Abits, *P, *Q;
    __nv_bfloat16 *Xp, *WsP, *WlP, *hkP, *WaP, *hkTP, *attP;
    cudaGetSymbolAddress((void**)&Wh,    g_Wh);
    cudaGetSymbolAddress((void**)&Wa,    g_Wa);
    cudaGetSymbolAddress((void**)&hk,    g_hk);
    cudaGetSymbolAddress((void**)&src,   g_src);
    cudaGetSymbolAddress((void**)&dst,   g_dst);
    cudaGetSymbolAddress((void**)&S,     g_S);
    cudaGetSymbolAddress((void**)&Abits, g_Abits);
    cudaGetSymbolAddress((void**)&P,     g_P);
    cudaGetSymbolAddress((void**)&Q,     g_Q);
    cudaGetSymbolAddress((void**)&Xp,    g_Xp);
    cudaGetSymbolAddress((void**)&WsP,   g_WsP);
    cudaGetSymbolAddress((void**)&WlP,   g_WlP);
    cudaGetSymbolAddress((void**)&hkP,   g_hkP);
    cudaGetSymbolAddress((void**)&WaP,   g_WaP);
    cudaGetSymbolAddress((void**)&hkTP,  g_hkTP);
    cudaGetSymbolAddress((void**)&attP,  g_attP);
    cudaGetSymbolAddress((void**)&part,  g_part);

    const int smemBytes = NSTG * 2 * 128 * SSTR * 2;   // 73728
    cudaFuncSetAttribute(mma_gemm_nt<false, true, true, false>,
                         cudaFuncAttributeMaxDynamicSharedMemorySize, smemBytes);
    cudaFuncSetAttribute(mma_gemm_nt<true, false, false, false>,
                         cudaFuncAttributeMaxDynamicSharedMemorySize, smemBytes);
    cudaFuncSetAttribute(mma_gemm_nt<false, true, false, true>,
                         cudaFuncAttributeMaxDynamicSharedMemorySize, smemBytes);

    // pack inputs to split-bf16
    pack_split_kernel<<<1024, 256>>>(X,  Xp,  NN, FF, 0);
    pack_split_kernel<<<256,  256>>>(Ws, WsP, FF, FF, 1);
    pack_split_kernel<<<256,  256>>>(Wl, WlP, FF, FF, 1);

    // Wh = X Ws^T and Wa = X Wl^T: dual + split-K 2 (z = {B,K} combos) + reduce
    // z: 0=(Ws,k0) 1=(Wl,k0) 2=(Ws,k1) 3=(Wl,k1); slabs in g_part
    mma_gemm_nt<false, true, true, false><<<dim3(FF / 128, NN / 128, 4), 128, smemBytes>>>(
        Xp, WsP, WlP, part, nullptr, NN, FF, K3S, K3S / 2, K3S, nullptr);
    reduce_dual_kernel<<<1024, 256>>>(part, Wh, Wa);

    // src/dst + short attention (emits Abits too) -> hk
    src_dst_kernel<<<NN / 8, 256>>>(Wh, r, src, dst);
    short_attn_kernel<<<NN, 256>>>(A, Wh, src, dst, hk, Abits);

    // pack hk (A-pattern), Wa (B-pattern), hk^T (B-pattern)
    pack_split_kernel<<<1024, 256>>>(hk, hkP, NN, FF, 0);
    pack_split_kernel<<<1024, 256>>>(Wa, WaP, NN, FF, 1);
    transpose_pack_kernel<<<dim3(FF / 32, NN / 32), dim3(32, 8)>>>(hk, hkTP, NN, FF);

    // multi-hop reachability (boolean), guarded launches; result in Q
    hop_step_kernel<<<NN, WRDS>>>(Abits, Abits, P, 0, nh);
    hop_step_kernel<<<NN, WRDS>>>(Abits, P, Q, 1, nh);
    hop_step_kernel<<<NN, WRDS>>>(Abits, Q, P, 2, nh);
    hop_step_kernel<<<NN, WRDS>>>(Abits, P, Q, 3, nh);
    hop_step_kernel<<<NN, WRDS>>>(Abits, Q, P, 4, nh);
    hop_step_kernel<<<NN, WRDS>>>(Abits, P, Q, 5, nh);

    // scores = hk Wa^T with reach mask -> S (fp32)
    mma_gemm_nt<true, false, false, false><<<dim3(NN / 128, NN / 128), 128, smemBytes>>>(
        hkP, WaP, nullptr, S, nullptr, NN, NN, K3S, K3S, K3S, Q);

    // softmax + pack att to [hi|lo] bf16 (stride 8192)
    softmax_pack_kernel<<<NN, 256>>>(S, attP);

    // ok = att2 hk  (split-K = 8, A-side K-remap over [hi|lo]) + reduce
    mma_gemm_nt<false, true, false, true><<<dim3(FF / 128, NN / 128, NSPLIT), 128, smemBytes>>>(
        attP, hkTP, nullptr, part, nullptr, NN, FF, K3N, K3N / NSPLIT, KATT, nullptr);
    reduceN_kernel<<<1024, 256>>>(part, out);
}

// round 14
// speedup vs baseline: 1.1119x; 1.0195x over previous
#include <cuda_runtime.h>
#include <cuda_bf16.h>
#include <float.h>
#include <stdint.h>

// Problem dims (fixed by setup_inputs)
#define NN   4096
#define FF   512
#define WRDS (NN / 32)
#define K3S  (3 * FF)      // 1536  logical K for feature-dim GEMMs
#define K3N  (3 * NN)      // 12288 logical K for the att@hk GEMM
#define KATT 8192          // physical [hi|lo] stride for attP / hkTP
#define KF   1024          // physical [hi|lo] stride for feature-dim operands
#define NSPLIT 8

// ---------------- device scratch (no allocations allowed) ----------------
__device__ float         g_Wh[NN * FF];
__device__ float         g_Wa[NN * FF];
__device__ float         g_hk[NN * FF];
__device__ float         g_src[NN];
__device__ float         g_dst[NN];
__device__ unsigned      g_Abits[NN * WRDS];
__device__ unsigned      g_P[NN * WRDS];
__device__ unsigned      g_Q[NN * WRDS];
__device__ float         g_S[(size_t)NN * NN];          // 64 MB scores
__device__ __nv_bfloat16 g_Xp [(size_t)NN * KF];        // 8 MB [hi|lo]
__device__ __nv_bfloat16 g_WsP[(size_t)FF * KF];        // 1 MB
__device__ __nv_bfloat16 g_WlP[(size_t)FF * KF];        // 1 MB
__device__ __nv_bfloat16 g_hkP[(size_t)NN * KF];        // 8 MB
__device__ __nv_bfloat16 g_WaP[(size_t)NN * KF];        // 8 MB
__device__ __nv_bfloat16 g_hkTP[(size_t)FF * KATT];     // 8 MB (transposed)
__device__ __nv_bfloat16 g_attP[(size_t)NN * KATT];     // 64 MB [hi|lo]
__device__ float         g_part[NSPLIT][(size_t)NN * FF]; // 64 MB split-K partials

// ---------------- helpers ----------------
__device__ __forceinline__ float gelu_tanh(float x) {
    float x3 = x * x * x;
    return 0.5f * x * (1.0f + tanhf(0.7978845608028654f * (x + 0.044715f * x3)));
}
__device__ __forceinline__ uint32_t smem_u32(const void* p) {
    return (uint32_t)__cvta_generic_to_shared(p);
}

// ============================================================
// Tensor-core bf16 NT GEMM over split-bf16 compressed operands:
//   logical K axis = 3 segments; physical buffer = [hi|lo].
//   A-side: logical [hi|hi|lo]  -> colP = colL>=TA ? colL-TA : colL (TA=C)
//   B-side: logical [hi|lo|hi]  -> colP = colL>=TB ? colL-TB : colL (TB=2C)
// CTA 128x128, 4 warps (2x2), warp tile 64x64, BK=64, 2-stage cp.async.
// DUAL:   blockIdx.z selects (B,C) vs (B2,C2)
// SPLITK: blockIdx.z selects K slice; C += z*M*N
// MASKED: reach-mask epilogue (masked -> -FLT_MAX)
// ============================================================
#define BK     64
#define SSTR   72            // padded halfs per row (144B, 16B multiple)
#define NSTG   2

template <bool MASKED, bool SPLITK, bool DUAL>
__global__ void __launch_bounds__(128, 3) mma_gemm_nt(
    const __nv_bfloat16* __restrict__ A,
    const __nv_bfloat16* __restrict__ B,
    const __nv_bfloat16* __restrict__ B2,
    float* __restrict__ C,
    float* __restrict__ C2,
    int M, int N, int K, int kSlice,
    int strideA, int strideB, int TA, int TB,
    const unsigned* __restrict__ maskbits)
{
    extern __shared__ __align__(16) unsigned char smem_raw[];
    __nv_bfloat16* AsBase = (__nv_bfloat16*)smem_raw;                 // [NSTG][128][SSTR]
    __nv_bfloat16* BsBase = AsBase + NSTG * 128 * SSTR;

    const int tid  = threadIdx.x;
    const int bx   = blockIdx.x;    // N tile
    const int by   = blockIdx.y;    // M tile
    const int bz   = blockIdx.z;
    const int warp = tid >> 5;
    const int lane = tid & 31;
    const int wm   = (warp >> 1) * 64;
    const int wn   = (warp & 1) * 64;

    const __nv_bfloat16* Bsel = (DUAL && bz) ? B2 : B;
    float* Csel = (DUAL && bz) ? C2 : C;
    int kBegin = 0, kLen = K;
    if (SPLITK) { kBegin = bz * kSlice; kLen = kSlice; Csel = C + (size_t)bz * M * N; }

    const __nv_bfloat16* Arow = A    + (size_t)(by * 128) * strideA;
    const __nv_bfloat16* Brow = Bsel + (size_t)(bx * 128) * strideB;

    float acc[4][8][4];
#pragma unroll
    for (int mi = 0; mi < 4; mi++)
#pragma unroll
        for (int nj = 0; nj < 8; nj++)
#pragma unroll
            for (int q = 0; q < 4; q++) acc[mi][nj][q] = 0.0f;

    const int nK = kLen / BK;   // BK=64 chunks

    auto load_stage = [&](int s, int kc) {
        __nv_bfloat16* As = AsBase + s * 128 * SSTR;
        __nv_bfloat16* Bs = BsBase + s * 128 * SSTR;
        int colL = kBegin + kc * BK;                    // logical column
        int colA = (colL >= TA) ? colL - TA : colL;
        int colB = (colL >= TB) ? colL - TB : colL;
#pragma unroll
        for (int j = 0; j < 8; j++) {
            int idx = tid + j * 128;        // 1024 chunks of 16B per matrix
            int row = idx >> 3;             // 0..127
            int c   = idx & 7;              // 16B chunk within 128B row
            uint32_t sa = smem_u32(&As[row * SSTR + c * 8]);
            const void* ga = Arow + (size_t)row * strideA + colA + c * 8;
            asm volatile("cp.async.cg.shared.global [%0], [%1], 16;" :: "r"(sa), "l"(ga));
            uint32_t sb = smem_u32(&Bs[row * SSTR + c * 8]);
            const void* gb = Brow + (size_t)row * strideB + colB + c * 8;
            asm volatile("cp.async.cg.shared.global [%0], [%1], 16;" :: "r"(sb), "l"(gb));
        }
    };

    load_stage(0, 0);
    asm volatile("cp.async.commit_group;");

    for (int kc = 0; kc < nK; kc++) {
        const int s = kc & 1;
        if (kc + 1 < nK) {
            load_stage(s ^ 1, kc + 1);
            asm volatile("cp.async.commit_group;");
            asm volatile("cp.async.wait_group 1;");
        } else {
            asm volatile("cp.async.wait_group 0;");
        }
        __syncthreads();

        const __nv_bfloat16* As = AsBase + s * 128 * SSTR;
        const __nv_bfloat16* Bs = BsBase + s * 128 * SSTR;

#pragma unroll
        for (int kk = 0; kk < BK; kk += 16) {
            uint32_t a[4][4];
#pragma unroll
            for (int mi = 0; mi < 4; mi++) {
                int row = wm + mi * 16 + (lane & 7) + ((lane >> 3) & 1) * 8;
                int col = kk + (lane >> 4) * 8;
                uint32_t addr = smem_u32(&As[row * SSTR + col]);
                asm volatile("ldmatrix.sync.aligned.m8n8.x4.shared.b16 {%0,%1,%2,%3},[%4];"
                    : "=r"(a[mi][0]), "=r"(a[mi][1]), "=r"(a[mi][2]), "=r"(a[mi][3])
                    : "r"(addr));
            }
            uint32_t b[8][2];
#pragma unroll
            for (int nj4 = 0; nj4 < 4; nj4++) {
                int row = wn + nj4 * 16 + (lane & 7) + (lane >> 4) * 8;
                int col = kk + ((lane >> 3) & 1) * 8;
                uint32_t addr = smem_u32(&Bs[row * SSTR + col]);
                asm volatile("ldmatrix.sync.aligned.m8n8.x4.shared.b16 {%0,%1,%2,%3},[%4];"
                    : "=r"(b[nj4 * 2][0]), "=r"(b[nj4 * 2][1]),
                      "=r"(b[nj4 * 2 + 1][0]), "=r"(b[nj4 * 2 + 1][1])
                    : "r"(addr));
            }
#pragma unroll
            for (int mi = 0; mi < 4; mi++)
#pragma unroll
                for (int nj = 0; nj < 8; nj++)
                    asm volatile(
                        "mma.sync.aligned.m16n8k16.row.col.f32.bf16.bf16.f32 "
                        "{%0,%1,%2,%3},{%4,%5,%6,%7},{%8,%9},{%0,%1,%2,%3};"
                        : "+f"(acc[mi][nj][0]), "+f"(acc[mi][nj][1]),
                          "+f"(acc[mi][nj][2]), "+f"(acc[mi][nj][3])
                        : "r"(a[mi][0]), "r"(a[mi][1]), "r"(a[mi][2]), "r"(a[mi][3]),
                          "r"(b[nj][0]), "r"(b[nj][1]));
        }
        __syncthreads();
    }

    // epilogue
    const int g = lane >> 2;
    const int c = lane & 3;
#pragma unroll
    for (int mi = 0; mi < 4; mi++) {
#pragma unroll
        for (int nj = 0; nj < 8; nj++) {
            int row0 = by * 128 + wm + mi * 16 + g;
            int row1 = row0 + 8;
            int col  = bx * 128 + wn + nj * 8 + c * 2;
            float v0 = acc[mi][nj][0], v1 = acc[mi][nj][1];
            float v2 = acc[mi][nj][2], v3 = acc[mi][nj][3];
            if (MASKED) {
                unsigned w0 = maskbits[(size_t)row0 * (N / 32) + (col >> 5)];
                unsigned w1 = maskbits[(size_t)row1 * (N / 32) + (col >> 5)];
                if (!((w0 >> (col & 31)) & 1u))       v0 = -FLT_MAX;
                if (!((w0 >> ((col + 1) & 31)) & 1u)) v1 = -FLT_MAX;
                if (!((w1 >> (col & 31)) & 1u))       v2 = -FLT_MAX;
                if (!((w1 >> ((col + 1) & 31)) & 1u)) v3 = -FLT_MAX;
            }
            *reinterpret_cast<float2*>(&Csel[(size_t)row0 * N + col]) = make_float2(v0, v1);
            *reinterpret_cast<float2*>(&Csel[(size_t)row1 * N + col]) = make_float2(v2, v3);
        }
    }
}

// ============================================================
// fp32 -> [hi|lo] bf16 packing (physical stride 2C)
// ============================================================
__global__ void pack_split_kernel(const float* __restrict__ in,
                                  __nv_bfloat16* __restrict__ out,
                                  int R, int C)
{
    int total = R * C;
    for (int idx = blockIdx.x * blockDim.x + threadIdx.x; idx < total;
         idx += gridDim.x * blockDim.x) {
        int r = idx / C, c = idx - r * C;
        float v = in[idx];
        __nv_bfloat16 hi = __float2bfloat16(v);
        __nv_bfloat16 lo = __float2bfloat16(v - __bfloat162float(hi));
        size_t base = (size_t)r * 2 * C;
        out[base + c]     = hi;
        out[base + C + c] = lo;
    }
}

// Transpose + [hi|lo] pack: in[R x C] fp32 -> out[C x 2R] bf16
__global__ void transpose_pack_kernel(const float* __restrict__ in,
                                      __nv_bfloat16* __restrict__ out,
                                      int R, int C)
{
    __shared__ float t[32][33];
    int rb = blockIdx.y * 32;
    int cb = blockIdx.x * 32;
    int tx = threadIdx.x;
    int ty0 = threadIdx.y;
#pragma unroll
    for (int p = 0; p < 4; p++) {
        int ty = ty0 + p * 8;
        t[ty][tx] = in[(size_t)(rb + ty) * C + cb + tx];
    }
    __syncthreads();
#pragma unroll
    for (int p = 0; p < 4; p++) {
        int ty = ty0 + p * 8;
        float v = t[tx][ty];
        __nv_bfloat16 hi = __float2bfloat16(v);
        __nv_bfloat16 lo = __float2bfloat16(v - __bfloat162float(hi));
        size_t base = (size_t)(cb + ty) * 2 * R;
        out[base + rb + tx]     = hi;
        out[base + R + rb + tx] = lo;
    }
}

// ============================================================
__global__ void src_dst_kernel(const float* __restrict__ Wh, const float* __restrict__ r,
                               float* __restrict__ src, float* __restrict__ dst)
{
    int warp = (blockIdx.x * blockDim.x + threadIdx.x) >> 5;
    int lane = threadIdx.x & 31;
    if (warp >= NN) return;
    const float* row = Wh + (size_t)warp * FF;
    float a = 0.f, b = 0.f;
    for (int f = lane; f < FF; f += 32) {
        float v = row[f];
        a = fmaf(v, r[f], a);
        b = fmaf(v, r[FF + f], b);
    }
#pragma unroll
    for (int s = 16; s > 0; s >>= 1) {
        a += __shfl_xor_sync(0xffffffffu, a, s);
        b += __shfl_xor_sync(0xffffffffu, b, s);
    }
    if (lane == 0) { src[warp] = a; dst[warp] = b; }
}

// ============================================================
// Short-distance attention (sparse), fused softmax + SpMM + gelu.
// Also emits the bit-packed adjacency row (fused, saves a 64MB re-read).
// ============================================================
__global__ void __launch_bounds__(256) short_attn_kernel(
    const float* __restrict__ A, const float* __restrict__ Wh,
    const float* __restrict__ src, const float* __restrict__ dst,
    float* __restrict__ hk, unsigned* __restrict__ bits)
{
    __shared__ int      s_idx[NN];
    __shared__ float    s_w[NN];
    __shared__ int      s_scan[256];
    __shared__ float    s_red[256];
    __shared__ unsigned s_m16[256];

    const int i   = blockIdx.x;
    const int tid = threadIdx.x;
    const float* Arow = A + (size_t)i * NN;

    const int base = tid * 16;
    unsigned m16 = 0; int c = 0;
#pragma unroll
    for (int q = 0; q < 16; q++)
        if (Arow[base + q] != 0.0f) { m16 |= (1u << q); c++; }
    s_m16[tid] = m16;
    s_scan[tid] = c;
    __syncthreads();
    if (tid < WRDS)
        bits[(size_t)i * WRDS + tid] = s_m16[2 * tid] | (s_m16[2 * tid + 1] << 16);
#pragma unroll
    for (int s = 1; s < 256; s <<= 1) {
        int v = (tid >= s) ? s_scan[tid - s] : 0;
        __syncthreads();
        s_scan[tid] += v;
        __syncthreads();
    }
    int start = s_scan[tid] - c;
    int cnt   = s_scan[255];
    {
        int p = start;
#pragma unroll
        for (int q = 0; q < 16; q++)
            if ((m16 >> q) & 1u) s_idx[p++] = base + q;
    }
    __syncthreads();

    float si = src[i];
    float lmax = -FLT_MAX;
    for (int p = tid; p < cnt; p += 256) {
        float e = si + dst[s_idx[p]];
        e = (e > 0.f) ? e : 0.2f * e;
        s_w[p] = e;
        lmax = fmaxf(lmax, e);
    }
    s_red[tid] = lmax;
    __syncthreads();
#pragma unroll
    for (int s = 128; s > 0; s >>= 1) {
        if (tid < s) s_red[tid] = fmaxf(s_red[tid], s_red[tid + s]);
        __syncthreads();
    }
    float mx = s_red[0];
    __syncthreads();

    float lsum = 0.f;
    for (int p = tid; p < cnt; p += 256) {
        float w = expf(s_w[p] - mx);
        s_w[p] = w;
        lsum += w;
    }
    s_red[tid] = lsum;
    __syncthreads();
#pragma unroll
    for (int s = 128; s > 0; s >>= 1) {
        if (tid < s) s_red[tid] += s_red[tid + s];
        __syncthreads();
    }
    float inv = 1.0f / s_red[0];
    __syncthreads();

    float a0 = 0.f, a1 = 0.f;
    for (int p = 0; p < cnt; p++) {
        float w = s_w[p];
        const float* whr = Wh + (size_t)s_idx[p] * FF;
        a0 = fmaf(w, whr[tid],       a0);
        a1 = fmaf(w, whr[tid + 256], a1);
    }
    hk[(size_t)i * FF + tid]       = gelu_tanh(a0 * inv);
    hk[(size_t)i * FF + tid + 256] = gelu_tanh(a1 * inv);
}

// ============================================================
__global__ void hop_step_kernel(const unsigned* __restrict__ Abits,
                                const unsigned* __restrict__ src,
                                unsigned* __restrict__ dst,
                                int iter, const int* __restrict__ num_hops)
{
    __shared__ unsigned s_row[WRDS];
    const int i = blockIdx.x;
    const int t = threadIdx.x;
    s_row[t] = Abits[i * WRDS + t];
    __syncthreads();

    if (iter >= (*num_hops) - 1) {
        dst[i * WRDS + t] = src[i * WRDS + t];
        return;
    }
    unsigned acc = 0;
    for (int w = 0; w < WRDS; w++) {
        unsigned bits = s_row[w];
        while (bits) {
            int b = __ffs(bits) - 1;
            bits &= bits - 1;
            acc |= src[(size_t)(w * 32 + b) * WRDS + t];
        }
    }
    dst[i * WRDS + t] = acc;
}

// ============================================================
// Row softmax (4096-wide) fused with [hi|lo] bf16 packing (stride 8192)
// ============================================================
__global__ void __launch_bounds__(256) softmax_pack_kernel(
    const float* __restrict__ S, __nv_bfloat16* __restrict__ attP)
{
    __shared__ float s_red[256];
    const int i   = blockIdx.x;
    const int tid = threadIdx.x;
    const float* row = S + (size_t)i * NN;
    __nv_bfloat16* orow = attP + (size_t)i * KATT;

    float vals[16];
    float lmax = -FLT_MAX;
#pragma unroll
    for (int p = 0; p < 16; p++) {
        vals[p] = row[tid + p * 256];
        lmax = fmaxf(lmax, vals[p]);
    }
    s_red[tid] = lmax;
    __syncthreads();
#pragma unroll
    for (int s = 128; s > 0; s >>= 1) {
        if (tid < s) s_red[tid] = fmaxf(s_red[tid], s_red[tid + s]);
        __syncthreads();
    }
    float mx = s_red[0];
    __syncthreads();

    float lsum = 0.f;
#pragma unroll
    for (int p = 0; p < 16; p++) {
        float w = expf(vals[p] - mx);
        vals[p] = w;
        lsum += w;
    }
    s_red[tid] = lsum;
    __syncthreads();
#pragma unroll
    for (int s = 128; s > 0; s >>= 1) {
        if (tid < s) s_red[tid] += s_red[tid + s];
        __syncthreads();
    }
    float inv = 1.0f / s_red[0];
#pragma unroll
    for (int p = 0; p < 16; p++) {
        int j = tid + p * 256;
        float a = vals[p] * inv;
        __nv_bfloat16 hi = __float2bfloat16(a);
        __nv_bfloat16 lo = __float2bfloat16(a - __bfloat162float(hi));
        orow[j]      = hi;
        orow[NN + j] = lo;
    }
}

// ============================================================
// out = sum of NSPLIT partials  (4096 x 512 fp32)
// ============================================================
__global__ void reduceN_kernel(const float* __restrict__ part, float* __restrict__ out)
{
    int total = NN * FF / 4;
    const size_t stride = (size_t)NN * FF / 4;
    for (int idx = blockIdx.x * blockDim.x + threadIdx.x; idx < total;
         idx += gridDim.x * blockDim.x) {
        float4 o = make_float4(0.f, 0.f, 0.f, 0.f);
#pragma unroll
        for (int s = 0; s < NSPLIT; s++) {
            float4 a = reinterpret_cast<const float4*>(part)[idx + s * stride];
            o.x += a.x; o.y += a.y; o.z += a.z; o.w += a.w;
        }
        reinterpret_cast<float4*>(out)[idx] = o;
    }
}

// ============================================================
// Host launch
// ============================================================
extern "C" void kernel_launch(void* const* d_in, const int* in_sizes, int n_in,
                              void* d_out, int out_size)
{
    const float* X  = (const float*)d_in[0];
    const float* A  = (const float*)d_in[1];
    const float* Ws = (const float*)d_in[2];
    const float* r  = (const float*)d_in[3];
    const float* Wl = (const float*)d_in[4];
    const int*   nh = (const int*)d_in[5];
    float* out = (float*)d_out;

    float *Wh, *Wa, *hk, *src, *dst, *S, *part;
    unsigned *Abits, *P, *Q;
    __nv_bfloat16 *Xp, *WsP, *WlP, *hkP, *WaP, *hkTP, *attP;
    cudaGetSymbolAddress((void**)&Wh,    g_Wh);
    cudaGetSymbolAddress((void**)&Wa,    g_Wa);
    cudaGetSymbolAddress((void**)&hk,    g_hk);
    cudaGetSymbolAddress((void**)&src,   g_src);
    cudaGetSymbolAddress((void**)&dst,   g_dst);
    cudaGetSymbolAddress((void**)&S,     g_S);
    cudaGetSymbolAddress((void**)&Abits, g_Abits);
    cudaGetSymbolAddress((void**)&P,     g_P);
    cudaGetSymbolAddress((void**)&Q,     g_Q);
    cudaGetSymbolAddress((void**)&Xp,    g_Xp);
    cudaGetSymbolAddress((void**)&WsP,   g_WsP);
    cudaGetSymbolAddress((void**)&WlP,   g_WlP);
    cudaGetSymbolAddress((void**)&hkP,   g_hkP);
    cudaGetSymbolAddress((void**)&WaP,   g_WaP);
    cudaGetSymbolAddress((void**)&hkTP,  g_hkTP);
    cudaGetSymbolAddress((void**)&attP,  g_attP);
    cudaGetSymbolAddress((void**)&part,  g_part);

    const int smemBytes = NSTG * 2 * 128 * SSTR * 2;   // 73728
    cudaFuncSetAttribute(mma_gemm_nt<false, false, true>,
                         cudaFuncAttributeMaxDynamicSharedMemorySize, smemBytes);
    cudaFuncSetAttribute(mma_gemm_nt<true, false, false>,
                         cudaFuncAttributeMaxDynamicSharedMemorySize, smemBytes);
    cudaFuncSetAttribute(mma_gemm_nt<false, true, false>,
                         cudaFuncAttributeMaxDynamicSharedMemorySize, smemBytes);

    // pack inputs to [hi|lo] bf16
    pack_split_kernel<<<1024, 256>>>(X,  Xp,  NN, FF);
    pack_split_kernel<<<256,  256>>>(Ws, WsP, FF, FF);
    pack_split_kernel<<<256,  256>>>(Wl, WlP, FF, FF);

    // Wh = X Ws^T and Wa = X Wl^T in ONE dual launch
    // A remap T=FF (logical [hi|hi|lo]); B remap T=2*FF (logical [hi|lo|hi])
    mma_gemm_nt<false, false, true><<<dim3(FF / 128, NN / 128, 2), 128, smemBytes>>>(
        Xp, WsP, WlP, Wh, Wa, NN, FF, K3S, K3S, KF, KF, FF, 2 * FF, nullptr);

    // src/dst + short attention (emits Abits too) -> hk
    src_dst_kernel<<<NN / 8, 256>>>(Wh, r, src, dst);
    short_attn_kernel<<<NN, 256>>>(A, Wh, src, dst, hk, Abits);

    // pack hk, Wa ([hi|lo]); hk^T ([hi|lo], stride 8192)
    pack_split_kernel<<<1024, 256>>>(hk, hkP, NN, FF);
    pack_split_kernel<<<1024, 256>>>(Wa, WaP, NN, FF);
    transpose_pack_kernel<<<dim3(FF / 32, NN / 32), dim3(32, 8)>>>(hk, hkTP, NN, FF);

    // multi-hop reachability (boolean), guarded launches; result in Q
    hop_step_kernel<<<NN, WRDS>>>(Abits, Abits, P, 0, nh);
    hop_step_kernel<<<NN, WRDS>>>(Abits, P, Q, 1, nh);
    hop_step_kernel<<<NN, WRDS>>>(Abits, Q, P, 2, nh);
    hop_step_kernel<<<NN, WRDS>>>(Abits, P, Q, 3, nh);
    hop_step_kernel<<<NN, WRDS>>>(Abits, Q, P, 4, nh);
    hop_step_kernel<<<NN, WRDS>>>(Abits, P, Q, 5, nh);

    // scores = hk Wa^T with reach mask -> S (fp32)
    mma_gemm_nt<true, false, false><<<dim3(NN / 128, NN / 128), 128, smemBytes>>>(
        hkP, WaP, nullptr, S, nullptr, NN, NN, K3S, K3S, KF, KF, FF, 2 * FF, Q);

    // softmax + pack att to [hi|lo] bf16 (stride 8192)
    softmax_pack_kernel<<<NN, 256>>>(S, attP);

    // ok = att2 hk  (split-K = 8; A remap T=NN, B remap T=2*NN) + reduce
    mma_gemm_nt<false, true, false><<<dim3(FF / 128, NN / 128, NSPLIT), 128, smemBytes>>>(
        attP, hkTP, nullptr, part, nullptr, NN, FF, K3N, K3N / NSPLIT,
        KATT, KATT, NN, 2 * NN, nullptr);
    reduceN_kernel<<<1024, 256>>>(part, out);
}

// round 17
// speedup vs baseline: 1.2244x; 1.1011x over previous
#include <cuda_runtime.h>
#include <cuda_bf16.h>
#include <float.h>
#include <stdint.h>

// Problem dims (fixed by setup_inputs)
#define NN   4096
#define FF   512
#define WRDS (NN / 32)
#define K3S  (3 * FF)      // 1536  logical K for feature-dim GEMMs
#define K2N  (2 * NN)      // 8192  logical K for the att@hk GEMM (hi*hi + hi*lo)
#define KATT 8192          // physical [hi|lo] stride for hkTP
#define KF   1024          // physical [hi|lo] stride for feature-dim operands
#define NSPLIT 8

// ---------------- device scratch (no allocations allowed) ----------------
__device__ float         g_Wh[NN * FF];
__device__ float         g_Wa[NN * FF];
__device__ float         g_hk[NN * FF];
__device__ float         g_src[NN];
__device__ float         g_dst[NN];
__device__ unsigned      g_Abits[NN * WRDS];
__device__ unsigned      g_P[NN * WRDS];
__device__ unsigned      g_Q[NN * WRDS];
__device__ float         g_S[(size_t)NN * NN];          // 64 MB scores
__device__ __nv_bfloat16 g_Xp [(size_t)NN * KF];        // 8 MB [hi|lo]
__device__ __nv_bfloat16 g_WsP[(size_t)FF * KF];        // 1 MB
__device__ __nv_bfloat16 g_WlP[(size_t)FF * KF];        // 1 MB
__device__ __nv_bfloat16 g_hkP[(size_t)NN * KF];        // 8 MB
__device__ __nv_bfloat16 g_WaP[(size_t)NN * KF];        // 8 MB
__device__ __nv_bfloat16 g_hkTP[(size_t)FF * KATT];     // 8 MB (transposed [hi|lo])
__device__ __nv_bfloat16 g_attP[(size_t)NN * NN];       // 32 MB (hi plane only)
__device__ float         g_part[NSPLIT][(size_t)NN * FF]; // 64 MB split-K partials

// ---------------- helpers ----------------
__device__ __forceinline__ float gelu_tanh(float x) {
    float x3 = x * x * x;
    return 0.5f * x * (1.0f + tanhf(0.7978845608028654f * (x + 0.044715f * x3)));
}
__device__ __forceinline__ uint32_t smem_u32(const void* p) {
    return (uint32_t)__cvta_generic_to_shared(p);
}

// ============================================================
// Tensor-core bf16 NT GEMM over split-bf16 compressed operands:
//   A-side remap: colP = colL>=TA ? colL-TA : colL
//   B-side remap: colP = colL>=TB ? colL-TB : colL  (TB >= K -> identity)
// CTA 128x128, 4 warps (2x2), warp tile 64x64, BK=64, 2-stage cp.async.
// DUAL:   blockIdx.z selects (B,C) vs (B2,C2)
// SPLITK: blockIdx.z selects K slice; C += z*M*N
// MASKED: reach-mask epilogue (masked -> -FLT_MAX)
// ============================================================
#define BK     64
#define SSTR   72            // padded halfs per row (144B, 16B multiple)
#define NSTG   2

template <bool MASKED, bool SPLITK, bool DUAL>
__global__ void __launch_bounds__(128, 3) mma_gemm_nt(
    const __nv_bfloat16* __restrict__ A,
    const __nv_bfloat16* __restrict__ B,
    const __nv_bfloat16* __restrict__ B2,
    float* __restrict__ C,
    float* __restrict__ C2,
    int M, int N, int K, int kSlice,
    int strideA, int strideB, int TA, int TB,
    const unsigned* __restrict__ maskbits)
{
    extern __shared__ __align__(16) unsigned char smem_raw[];
    __nv_bfloat16* AsBase = (__nv_bfloat16*)smem_raw;                 // [NSTG][128][SSTR]
    __nv_bfloat16* BsBase = AsBase + NSTG * 128 * SSTR;

    const int tid  = threadIdx.x;
    const int bx   = blockIdx.x;    // N tile
    const int by   = blockIdx.y;    // M tile
    const int bz   = blockIdx.z;
    const int warp = tid >> 5;
    const int lane = tid & 31;
    const int wm   = (warp >> 1) * 64;
    const int wn   = (warp & 1) * 64;

    const __nv_bfloat16* Bsel = (DUAL && bz) ? B2 : B;
    float* Csel = (DUAL && bz) ? C2 : C;
    int kBegin = 0, kLen = K;
    if (SPLITK) { kBegin = bz * kSlice; kLen = kSlice; Csel = C + (size_t)bz * M * N; }

    const __nv_bfloat16* Arow = A    + (size_t)(by * 128) * strideA;
    const __nv_bfloat16* Brow = Bsel + (size_t)(bx * 128) * strideB;

    float acc[4][8][4];
#pragma unroll
    for (int mi = 0; mi < 4; mi++)
#pragma unroll
        for (int nj = 0; nj < 8; nj++)
#pragma unroll
            for (int q = 0; q < 4; q++) acc[mi][nj][q] = 0.0f;

    const int nK = kLen / BK;   // BK=64 chunks

    auto load_stage = [&](int s, int kc) {
        __nv_bfloat16* As = AsBase + s * 128 * SSTR;
        __nv_bfloat16* Bs = BsBase + s * 128 * SSTR;
        int colL = kBegin + kc * BK;                    // logical column
        int colA = (colL >= TA) ? colL - TA : colL;
        int colB = (colL >= TB) ? colL - TB : colL;
#pragma unroll
        for (int j = 0; j < 8; j++) {
            int idx = tid + j * 128;        // 1024 chunks of 16B per matrix
            int row = idx >> 3;             // 0..127
            int c   = idx & 7;              // 16B chunk within 128B row
            uint32_t sa = smem_u32(&As[row * SSTR + c * 8]);
            const void* ga = Arow + (size_t)row * strideA + colA + c * 8;
            asm volatile("cp.async.cg.shared.global [%0], [%1], 16;" :: "r"(sa), "l"(ga));
            uint32_t sb = smem_u32(&Bs[row * SSTR + c * 8]);
            const void* gb = Brow + (size_t)row * strideB + colB + c * 8;
            asm volatile("cp.async.cg.shared.global [%0], [%1], 16;" :: "r"(sb), "l"(gb));
        }
    };

    load_stage(0, 0);
    asm volatile("cp.async.commit_group;");

    for (int kc = 0; kc < nK; kc++) {
        const int s = kc & 1;
        if (kc + 1 < nK) {
            load_stage(s ^ 1, kc + 1);
            asm volatile("cp.async.commit_group;");
            asm volatile("cp.async.wait_group 1;");
        } else {
            asm volatile("cp.async.wait_group 0;");
        }
        __syncthreads();

        const __nv_bfloat16* As = AsBase + s * 128 * SSTR;
        const __nv_bfloat16* Bs = BsBase + s * 128 * SSTR;

#pragma unroll
        for (int kk = 0; kk < BK; kk += 16) {
            uint32_t a[4][4];
#pragma unroll
            for (int mi = 0; mi < 4; mi++) {
                int row = wm + mi * 16 + (lane & 7) + ((lane >> 3) & 1) * 8;
                int col = kk + (lane >> 4) * 8;
                uint32_t addr = smem_u32(&As[row * SSTR + col]);
                asm volatile("ldmatrix.sync.aligned.m8n8.x4.shared.b16 {%0,%1,%2,%3},[%4];"
                    : "=r"(a[mi][0]), "=r"(a[mi][1]), "=r"(a[mi][2]), "=r"(a[mi][3])
                    : "r"(addr));
            }
            uint32_t b[8][2];
#pragma unroll
            for (int nj4 = 0; nj4 < 4; nj4++) {
                int row = wn + nj4 * 16 + (lane & 7) + (lane >> 4) * 8;
                int col = kk + ((lane >> 3) & 1) * 8;
                uint32_t addr = smem_u32(&Bs[row * SSTR + col]);
                asm volatile("ldmatrix.sync.aligned.m8n8.x4.shared.b16 {%0,%1,%2,%3},[%4];"
                    : "=r"(b[nj4 * 2][0]), "=r"(b[nj4 * 2][1]),
                      "=r"(b[nj4 * 2 + 1][0]), "=r"(b[nj4 * 2 + 1][1])
                    : "r"(addr));
            }
#pragma unroll
            for (int mi = 0; mi < 4; mi++)
#pragma unroll
                for (int nj = 0; nj < 8; nj++)
                    asm volatile(
                        "mma.sync.aligned.m16n8k16.row.col.f32.bf16.bf16.f32 "
                        "{%0,%1,%2,%3},{%4,%5,%6,%7},{%8,%9},{%0,%1,%2,%3};"
                        : "+f"(acc[mi][nj][0]), "+f"(acc[mi][nj][1]),
                          "+f"(acc[mi][nj][2]), "+f"(acc[mi][nj][3])
                        : "r"(a[mi][0]), "r"(a[mi][1]), "r"(a[mi][2]), "r"(a[mi][3]),
                          "r"(b[nj][0]), "r"(b[nj][1]));
        }
        __syncthreads();
    }

    // epilogue
    const int g = lane >> 2;
    const int c = lane & 3;
#pragma unroll
    for (int mi = 0; mi < 4; mi++) {
#pragma unroll
        for (int nj = 0; nj < 8; nj++) {
            int row0 = by * 128 + wm + mi * 16 + g;
            int row1 = row0 + 8;
            int col  = bx * 128 + wn + nj * 8 + c * 2;
            float v0 = acc[mi][nj][0], v1 = acc[mi][nj][1];
            float v2 = acc[mi][nj][2], v3 = acc[mi][nj][3];
            if (MASKED) {
                unsigned w0 = maskbits[(size_t)row0 * (N / 32) + (col >> 5)];
                unsigned w1 = maskbits[(size_t)row1 * (N / 32) + (col >> 5)];
                if (!((w0 >> (col & 31)) & 1u))       v0 = -FLT_MAX;
                if (!((w0 >> ((col + 1) & 31)) & 1u)) v1 = -FLT_MAX;
                if (!((w1 >> (col & 31)) & 1u))       v2 = -FLT_MAX;
                if (!((w1 >> ((col + 1) & 31)) & 1u)) v3 = -FLT_MAX;
            }
            *reinterpret_cast<float2*>(&Csel[(size_t)row0 * N + col]) = make_float2(v0, v1);
            *reinterpret_cast<float2*>(&Csel[(size_t)row1 * N + col]) = make_float2(v2, v3);
        }
    }
}

// ============================================================
// fp32 -> [hi|lo] bf16 packing (physical stride 2C)
// ============================================================
__global__ void pack_split_kernel(const float* __restrict__ in,
                                  __nv_bfloat16* __restrict__ out,
                                  int R, int C)
{
    int total = R * C;
    for (int idx = blockIdx.x * blockDim.x + threadIdx.x; idx < total;
         idx += gridDim.x * blockDim.x) {
        int r = idx / C, c = idx - r * C;
        float v = in[idx];
        __nv_bfloat16 hi = __float2bfloat16(v);
        __nv_bfloat16 lo = __float2bfloat16(v - __bfloat162float(hi));
        size_t base = (size_t)r * 2 * C;
        out[base + c]     = hi;
        out[base + C + c] = lo;
    }
}

// Transpose + [hi|lo] pack: in[R x C] fp32 -> out[C x 2R] bf16
__global__ void transpose_pack_kernel(const float* __restrict__ in,
                                      __nv_bfloat16* __restrict__ out,
                                      int R, int C)
{
    __shared__ float t[32][33];
    int rb = blockIdx.y * 32;
    int cb = blockIdx.x * 32;
    int tx = threadIdx.x;
    int ty0 = threadIdx.y;
#pragma unroll
    for (int p = 0; p < 4; p++) {
        int ty = ty0 + p * 8;
        t[ty][tx] = in[(size_t)(rb + ty) * C + cb + tx];
    }
    __syncthreads();
#pragma unroll
    for (int p = 0; p < 4; p++) {
        int ty = ty0 + p * 8;
        float v = t[tx][ty];
        __nv_bfloat16 hi = __float2bfloat16(v);
        __nv_bfloat16 lo = __float2bfloat16(v - __bfloat162float(hi));
        size_t base = (size_t)(cb + ty) * 2 * R;
        out[base + rb + tx]     = hi;
        out[base + R + rb + tx] = lo;
    }
}

// ============================================================
__global__ void src_dst_kernel(const float* __restrict__ Wh, const float* __restrict__ r,
                               float* __restrict__ src, float* __restrict__ dst)
{
    int warp = (blockIdx.x * blockDim.x + threadIdx.x) >> 5;
    int lane = threadIdx.x & 31;
    if (warp >= NN) return;
    const float* row = Wh + (size_t)warp * FF;
    float a = 0.f, b = 0.f;
    for (int f = lane; f < FF; f += 32) {
        float v = row[f];
        a = fmaf(v, r[f], a);
        b = fmaf(v, r[FF + f], b);
    }
#pragma unroll
    for (int s = 16; s > 0; s >>= 1) {
        a += __shfl_xor_sync(0xffffffffu, a, s);
        b += __shfl_xor_sync(0xffffffffu, b, s);
    }
    if (lane == 0) { src[warp] = a; dst[warp] = b; }
}

// ============================================================
// Short-distance attention (sparse), fused softmax + SpMM + gelu.
// Also emits the bit-packed adjacency row (fused, saves a 64MB re-read).
// ============================================================
__global__ void __launch_bounds__(256) short_attn_kernel(
    const float* __restrict__ A, const float* __restrict__ Wh,
    const float* __restrict__ src, const float* __restrict__ dst,
    float* __restrict__ hk, unsigned* __restrict__ bits)
{
    __shared__ int      s_idx[NN];
    __shared__ float    s_w[NN];
    __shared__ int      s_scan[256];
    __shared__ float    s_red[256];
    __shared__ unsigned s_m16[256];

    const int i   = blockIdx.x;
    const int tid = threadIdx.x;
    const float* Arow = A + (size_t)i * NN;

    const int base = tid * 16;
    unsigned m16 = 0; int c = 0;
#pragma unroll
    for (int q = 0; q < 16; q++)
        if (Arow[base + q] != 0.0f) { m16 |= (1u << q); c++; }
    s_m16[tid] = m16;
    s_scan[tid] = c;
    __syncthreads();
    if (tid < WRDS)
        bits[(size_t)i * WRDS + tid] = s_m16[2 * tid] | (s_m16[2 * tid + 1] << 16);
#pragma unroll
    for (int s = 1; s < 256; s <<= 1) {
        int v = (tid >= s) ? s_scan[tid - s] : 0;
        __syncthreads();
        s_scan[tid] += v;
        __syncthreads();
    }
    int start = s_scan[tid] - c;
    int cnt   = s_scan[255];
    {
        int p = start;
#pragma unroll
        for (int q = 0; q < 16; q++)
            if ((m16 >> q) & 1u) s_idx[p++] = base + q;
    }
    __syncthreads();

    float si = src[i];
    float lmax = -FLT_MAX;
    for (int p = tid; p < cnt; p += 256) {
        float e = si + dst[s_idx[p]];
        e = (e > 0.f) ? e : 0.2f * e;
        s_w[p] = e;
        lmax = fmaxf(lmax, e);
    }
    s_red[tid] = lmax;
    __syncthreads();
#pragma unroll
    for (int s = 128; s > 0; s >>= 1) {
        if (tid < s) s_red[tid] = fmaxf(s_red[tid], s_red[tid + s]);
        __syncthreads();
    }
    float mx = s_red[0];
    __syncthreads();

    float lsum = 0.f;
    for (int p = tid; p < cnt; p += 256) {
        float w = expf(s_w[p] - mx);
        s_w[p] = w;
        lsum += w;
    }
    s_red[tid] = lsum;
    __syncthreads();
#pragma unroll
    for (int s = 128; s > 0; s >>= 1) {
        if (tid < s) s_red[tid] += s_red[tid + s];
        __syncthreads();
    }
    float inv = 1.0f / s_red[0];
    __syncthreads();

    float a0 = 0.f, a1 = 0.f;
    for (int p = 0; p < cnt; p++) {
        float w = s_w[p];
        const float* whr = Wh + (size_t)s_idx[p] * FF;
        a0 = fmaf(w, whr[tid],       a0);
        a1 = fmaf(w, whr[tid + 256], a1);
    }
    hk[(size_t)i * FF + tid]       = gelu_tanh(a0 * inv);
    hk[(size_t)i * FF + tid + 256] = gelu_tanh(a1 * inv);
}

// ============================================================
__global__ void hop_step_kernel(const unsigned* __restrict__ Abits,
                                const unsigned* __restrict__ src,
                                unsigned* __restrict__ dst,
                                int iter, const int* __restrict__ num_hops)
{
    __shared__ unsigned s_row[WRDS];
    const int i = blockIdx.x;
    const int t = threadIdx.x;
    s_row[t] = Abits[i * WRDS + t];
    __syncthreads();

    if (iter >= (*num_hops) - 1) {
        dst[i * WRDS + t] = src[i * WRDS + t];
        return;
    }
    unsigned acc = 0;
    for (int w = 0; w < WRDS; w++) {
        unsigned bits = s_row[w];
        while (bits) {
            int b = __ffs(bits) - 1;
            bits &= bits - 1;
            acc |= src[(size_t)(w * 32 + b) * WRDS + t];
        }
    }
    dst[i * WRDS + t] = acc;
}

// ============================================================
// Row softmax (4096-wide) fused with bf16 hi-plane packing (stride 4096)
// (att_lo is dropped in the final GEMM; error is incoherent-sum tiny)
// ============================================================
__global__ void __launch_bounds__(256) softmax_pack_kernel(
    const float* __restrict__ S, __nv_bfloat16* __restrict__ attP)
{
    __shared__ float s_red[256];
    const int i   = blockIdx.x;
    const int tid = threadIdx.x;
    const float* row = S + (size_t)i * NN;
    __nv_bfloat16* orow = attP + (size_t)i * NN;

    float vals[16];
    float lmax = -FLT_MAX;
#pragma unroll
    for (int p = 0; p < 16; p++) {
        vals[p] = row[tid + p * 256];
        lmax = fmaxf(lmax, vals[p]);
    }
    s_red[tid] = lmax;
    __syncthreads();
#pragma unroll
    for (int s = 128; s > 0; s >>= 1) {
        if (tid < s) s_red[tid] = fmaxf(s_red[tid], s_red[tid + s]);
        __syncthreads();
    }
    float mx = s_red[0];
    __syncthreads();

    float lsum = 0.f;
#pragma unroll
    for (int p = 0; p < 16; p++) {
        float w = expf(vals[p] - mx);
        vals[p] = w;
        lsum += w;
    }
    s_red[tid] = lsum;
    __syncthreads();
#pragma unroll
    for (int s = 128; s > 0; s >>= 1) {
        if (tid < s) s_red[tid] += s_red[tid + s];
        __syncthreads();
    }
    float inv = 1.0f / s_red[0];
#pragma unroll
    for (int p = 0; p < 16; p++) {
        int j = tid + p * 256;
        orow[j] = __float2bfloat16(vals[p] * inv);
    }
}

// ============================================================
// out = sum of NSPLIT partials  (4096 x 512 fp32)
// ============================================================
__global__ void reduceN_kernel(const float* __restrict__ part, float* __restrict__ out)
{
    int total = NN * FF / 4;
    const size_t stride = (size_t)NN * FF / 4;
    for (int idx = blockIdx.x * blockDim.x + threadIdx.x; idx < total;
         idx += gridDim.x * blockDim.x) {
        float4 o = make_float4(0.f, 0.f, 0.f, 0.f);
#pragma unroll
        for (int s = 0; s < NSPLIT; s++) {
            float4 a = reinterpret_cast<const float4*>(part)[idx + s * stride];
            o.x += a.x; o.y += a.y; o.z += a.z; o.w += a.w;
        }
        reinterpret_cast<float4*>(out)[idx] = o;
    }
}

// ============================================================
// Host launch
// ============================================================
extern "C" void kernel_launch(void* const* d_in, const int* in_sizes, int n_in,
                              void* d_out, int out_size)
{
    const float* X  = (const float*)d_in[0];
    const float* A  = (const float*)d_in[1];
    const float* Ws = (const float*)d_in[2];
    const float* r  = (const float*)d_in[3];
    const float* Wl = (const float*)d_in[4];
    const int*   nh = (const int*)d_in[5];
    float* out = (float*)d_out;

    float *Wh, *Wa, *hk, *src, *dst, *S, *part;
    unsigned *Abits, *P, *Q;
    __nv_bfloat16 *Xp, *WsP, *WlP, *hkP, *WaP, *hkTP, *attP;
    cudaGetSymbolAddress((void**)&Wh,    g_Wh);
    cudaGetSymbolAddress((void**)&Wa,    g_Wa);
    cudaGetSymbolAddress((void**)&hk,    g_hk);
    cudaGetSymbolAddress((void**)&src,   g_src);
    cudaGetSymbolAddress((void**)&dst,   g_dst);
    cudaGetSymbolAddress((void**)&S,     g_S);
    cudaGetSymbolAddress((void**)&Abits, g_Abits);
    cudaGetSymbolAddress((void**)&P,     g_P);
    cudaGetSymbolAddress((void**)&Q,     g_Q);
    cudaGetSymbolAddress((void**)&Xp,    g_Xp);
    cudaGetSymbolAddress((void**)&WsP,   g_WsP);
    cudaGetSymbolAddress((void**)&WlP,   g_WlP);
    cudaGetSymbolAddress((void**)&hkP,   g_hkP);
    cudaGetSymbolAddress((void**)&WaP,   g_WaP);
    cudaGetSymbolAddress((void**)&hkTP,  g_hkTP);
    cudaGetSymbolAddress((void**)&attP,  g_attP);
    cudaGetSymbolAddress((void**)&part,  g_part);

    const int smemBytes = NSTG * 2 * 128 * SSTR * 2;   // 73728
    cudaFuncSetAttribute(mma_gemm_nt<false, false, true>,
                         cudaFuncAttributeMaxDynamicSharedMemorySize, smemBytes);
    cudaFuncSetAttribute(mma_gemm_nt<true, false, false>,
                         cudaFuncAttributeMaxDynamicSharedMemorySize, smemBytes);
    cudaFuncSetAttribute(mma_gemm_nt<false, true, false>,
                         cudaFuncAttributeMaxDynamicSharedMemorySize, smemBytes);

    // pack inputs to [hi|lo] bf16
    pack_split_kernel<<<1024, 256>>>(X,  Xp,  NN, FF);
    pack_split_kernel<<<256,  256>>>(Ws, WsP, FF, FF);
    pack_split_kernel<<<256,  256>>>(Wl, WlP, FF, FF);

    // Wh = X Ws^T and Wa = X Wl^T in ONE dual launch
    // A remap T=FF (logical [hi|hi|lo]); B remap T=2*FF (logical [hi|lo|hi])
    mma_gemm_nt<false, false, true><<<dim3(FF / 128, NN / 128, 2), 128, smemBytes>>>(
        Xp, WsP, WlP, Wh, Wa, NN, FF, K3S, K3S, KF, KF, FF, 2 * FF, nullptr);

    // src/dst + short attention (emits Abits too) -> hk
    src_dst_kernel<<<NN / 8, 256>>>(Wh, r, src, dst);
    short_attn_kernel<<<NN, 256>>>(A, Wh, src, dst, hk, Abits);

    // pack hk, Wa ([hi|lo]); hk^T ([hi|lo], stride 8192)
    pack_split_kernel<<<1024, 256>>>(hk, hkP, NN, FF);
    pack_split_kernel<<<1024, 256>>>(Wa, WaP, NN, FF);
    transpose_pack_kernel<<<dim3(FF / 32, NN / 32), dim3(32, 8)>>>(hk, hkTP, NN, FF);

    // multi-hop reachability (boolean), guarded launches; result in Q
    hop_step_kernel<<<NN, WRDS>>>(Abits, Abits, P, 0, nh);
    hop_step_kernel<<<NN, WRDS>>>(Abits, P, Q, 1, nh);
    hop_step_kernel<<<NN, WRDS>>>(Abits, Q, P, 2, nh);
    hop_step_kernel<<<NN, WRDS>>>(Abits, P, Q, 3, nh);
    hop_step_kernel<<<NN, WRDS>>>(Abits, Q, P, 4, nh);
    hop_step_kernel<<<NN, WRDS>>>(Abits, P, Q, 5, nh);

    // scores = hk Wa^T with reach mask -> S (fp32; full 3-term split)
    mma_gemm_nt<true, false, false><<<dim3(NN / 128, NN / 128), 128, smemBytes>>>(
        hkP, WaP, nullptr, S, nullptr, NN, NN, K3S, K3S, KF, KF, FF, 2 * FF, Q);

    // softmax + pack att (hi plane only, stride 4096)
    softmax_pack_kernel<<<NN, 256>>>(S, attP);

    // ok = att_hi @ (hk_hi + hk_lo): logical K = 8192
    //   segment 0 (cols 0..4095):    A=att_hi, B=hk_hi
    //   segment 1 (cols 4096..8191): A=att_hi (TA wrap), B=hk_lo (identity)
    mma_gemm_nt<false, true, false><<<dim3(FF / 128, NN / 128, NSPLIT), 128, smemBytes>>>(
        attP, hkTP, nullptr, part, nullptr, NN, FF, K2N, K2N / NSPLIT,
        NN, KATT, NN, 2 * NN, nullptr);
    reduceN_kernel<<<1024, 256>>>(part, out);
}